// round 12
// baseline (speedup 1.0000x reference)
#include <cuda_runtime.h>
#include <cuda_fp16.h>
#include <math.h>
#include <stdint.h>

#define Bb 4
#define Ss 2048
#define Dd 1024
#define Hh 16
#define DK 64

static const size_t OUT_ELEMS = (size_t)Bb * Ss * Dd;   // 8388608

// Scratch (device globals — allocation-free per harness rules)
__device__ __half g_h[(size_t)Bb * Ss * Dd];
__device__ __half g_q[(size_t)Bb * Hh * Ss * DK];
__device__ __half g_k[(size_t)Bb * Hh * Ss * DK];
__device__ __half g_vt[(size_t)Bb * Hh * DK * Ss];  // V^T: [bh][d][s]
__device__ __half g_o[(size_t)Bb * Ss * Dd];
__device__ __half g_wq[(size_t)Dd * Dd];
__device__ __half g_wk[(size_t)Dd * Dd];
__device__ __half g_wv[(size_t)Dd * Dd];
__device__ __half g_wf[(size_t)Dd * Dd];
__device__ uint32_t g_mbits[(size_t)Bb * Ss * (Ss / 32)];   // 1 bit / key

// ---------------------------------------------------------------------------
#define CP16(dst_u32, src_ptr) \
    asm volatile("cp.async.cg.shared.global [%0], [%1], 16;\n" :: "r"(dst_u32), "l"(src_ptr))
#define CP_COMMIT() asm volatile("cp.async.commit_group;\n" ::)
#define CP_WAIT(N)  asm volatile("cp.async.wait_group %0;\n" :: "n"(N))

#define MMA_F16(acc, a, b) \
    asm volatile( \
        "mma.sync.aligned.m16n8k16.row.col.f32.f16.f16.f32 " \
        "{%0,%1,%2,%3}, {%4,%5,%6,%7}, {%8,%9}, {%0,%1,%2,%3};" \
        : "+f"(acc[0]), "+f"(acc[1]), "+f"(acc[2]), "+f"(acc[3]) \
        : "r"(a[0]), "r"(a[1]), "r"(a[2]), "r"(a[3]), "r"(b[0]), "r"(b[1]))

#define LDSM4(R0, R1, R2, R3, ADDR) \
    asm volatile("ldmatrix.sync.aligned.m8n8.x4.shared.b16 {%0,%1,%2,%3}, [%4];" \
        : "=r"(R0), "=r"(R1), "=r"(R2), "=r"(R3) : "r"(ADDR))

__device__ __forceinline__ uint32_t packh2(float lo, float hi) {
    __half2 h = __floats2half2_rn(lo, hi);
    return *(uint32_t*)&h;
}
// Q is pre-scaled by 0.125*log2(e), so exp(0.125*s_raw) = ex2(s)
#define EXP_SC 0.1803368801111244f
__device__ __forceinline__ float ex2f(float x) {
    float r;
    asm("ex2.approx.f32 %0, %1;" : "=f"(r) : "f"(x));
    return r;
}

__device__ __forceinline__ float blockReduceSum(float val) {
    __shared__ float sh[32];
    int lane = threadIdx.x & 31, wid = threadIdx.x >> 5;
    #pragma unroll
    for (int o = 16; o; o >>= 1) val += __shfl_down_sync(0xffffffffu, val, o);
    if (lane == 0) sh[wid] = val;
    __syncthreads();
    val = (threadIdx.x < 8) ? sh[lane] : 0.0f;
    if (wid == 0) {
        #pragma unroll
        for (int o = 4; o; o >>= 1) val += __shfl_down_sync(0xffffffffu, val, o);
    }
    __syncthreads();
    return val;
}

// ---------------------------------------------------------------------------
// mask (int32) -> bitmap (1 bit per element), warp-ballot, fully coalesced
// ---------------------------------------------------------------------------
__global__ __launch_bounds__(256) void mask_bits_kernel(
    const int* __restrict__ mask, uint32_t* __restrict__ bits)
{
    int warp = threadIdx.x >> 5, lane = threadIdx.x & 31;
    size_t w0 = (size_t)blockIdx.x * 256 + warp * 32;
    #pragma unroll 4
    for (int i = 0; i < 32; i++) {
        size_t w = w0 + i;
        int v = mask[w * 32 + lane];
        uint32_t bm = __ballot_sync(0xffffffffu, v != 0);
        if (lane == 0) bits[w] = bm;
    }
}

// ---------------------------------------------------------------------------
// LayerNorm — writes fp16 h
// ---------------------------------------------------------------------------
__global__ __launch_bounds__(256) void ln_kernel(
    const float* __restrict__ x, const float* __restrict__ a,
    const float* __restrict__ bvec, __half* __restrict__ h)
{
    int row = blockIdx.x;
    const float4* xr = (const float4*)(x + (size_t)row * Dd);
    float4 v = xr[threadIdx.x];

    float s = blockReduceSum(v.x + v.y + v.z + v.w);
    __shared__ float mean_s, inv_s;
    if (threadIdx.x == 0) mean_s = s * (1.0f / Dd);
    __syncthreads();
    float mean = mean_s;

    float dx = v.x - mean, dy = v.y - mean, dz = v.z - mean, dw = v.w - mean;
    float sq = blockReduceSum(dx * dx + dy * dy + dz * dz + dw * dw);
    if (threadIdx.x == 0) inv_s = 1.0f / (sqrtf(sq * (1.0f / (Dd - 1))) + 1e-6f);
    __syncthreads();
    float inv = inv_s;

    float4 av = ((const float4*)a)[threadIdx.x];
    float4 bv = ((const float4*)bvec)[threadIdx.x];
    uint2 o;
    o.x = packh2(av.x * dx * inv + bv.x, av.y * dy * inv + bv.y);
    o.y = packh2(av.z * dz * inv + bv.z, av.w * dw * inv + bv.w);
    *(uint2*)(h + (size_t)row * Dd + threadIdx.x * 4) = o;
}

// All 4 weights in one launch; blockIdx.y selects the pair.
__global__ __launch_bounds__(256) void whalf4_kernel(
    const float* __restrict__ s0, const float* __restrict__ s1,
    const float* __restrict__ s2, const float* __restrict__ s3,
    __half* __restrict__ d0, __half* __restrict__ d1,
    __half* __restrict__ d2, __half* __restrict__ d3)
{
    int z = blockIdx.y;
    const float* src = (z == 0) ? s0 : (z == 1) ? s1 : (z == 2) ? s2 : s3;
    __half* dst      = (z == 0) ? d0 : (z == 1) ? d1 : (z == 2) ? d2 : d3;
    int i = blockIdx.x * 256 + threadIdx.x;
    float4 v = ((const float4*)src)[i];
    uint2 o;
    o.x = packh2(v.x, v.y);
    o.y = packh2(v.z, v.w);
    *(uint2*)(dst + (size_t)i * 4) = o;
}

// ---------------------------------------------------------------------------
// fp16 GEMM core (ldmatrix fragments). BM=128, BN=128, BK=64, 8 warps.
// QKV==1: blockIdx.z selects Q/K/V weight + scatter epilogue (Q pre-scaled).
// QKV==0: FC (+bias+residual, fp32 out).
// ---------------------------------------------------------------------------
template<int QKV>
__global__ __launch_bounds__(256, 2) void gemm_h(
    const __half* __restrict__ A,
    const __half* __restrict__ w0, const __half* __restrict__ w1,
    const __half* __restrict__ w2,
    const float* __restrict__ b0, const float* __restrict__ b1,
    const float* __restrict__ b2,
    const float* __restrict__ xres,
    void* __restrict__ c0, void* __restrict__ c1, void* __restrict__ c2)
{
    extern __shared__ __align__(16) __half hsm[];
    const int AST = 9216, BOFF = 18432;    // half units
    uint32_t smem_u = (uint32_t)__cvta_generic_to_shared(hsm);

    int z = QKV ? blockIdx.z : 0;
    const __half* B    = (z == 0) ? w0 : (z == 1) ? w1 : w2;
    const float* bias  = (z == 0) ? b0 : (z == 1) ? b1 : b2;
    float osc = (QKV && z == 0) ? EXP_SC : 1.0f;   // fold exp scale into Q

    const int K = Dd;
    int tid = threadIdx.x;
    int m0 = blockIdx.y * 128, n0 = blockIdx.x * 128;
    int lane = tid & 31, warp = tid >> 5;
    int wm = warp >> 2, wn = warp & 3;
    int g = lane >> 2, tig = lane & 3;
    int mb = wm * 64, nb = wn * 32;

    int aRow = lane & 15;
    int aCol = (lane >> 4) << 3;
    int bRow = ((lane >> 4) << 3) + (lane & 7);
    int bCol = ((lane >> 3) & 1) << 3;

    float acc[4][4][4] = {};

    int r_ld = tid >> 3;
    int c_ld = (tid & 7) * 8;

    auto loadTile = [&](int kt, int s) {
        int kof = kt * 64;
        #pragma unroll
        for (int i = 0; i < 4; i++) {
            int r = r_ld + i * 32;
            CP16(smem_u + (s * AST + r * 72 + c_ld) * 2,
                 A + (size_t)(m0 + r) * K + kof + c_ld);
        }
        #pragma unroll
        for (int i = 0; i < 4; i++) {
            int r = r_ld + i * 32;
            CP16(smem_u + (BOFF + s * AST + r * 72 + c_ld) * 2,
                 B + (size_t)(n0 + r) * K + kof + c_ld);
        }
    };

    loadTile(0, 0);
    CP_COMMIT();

    for (int it = 0; it < 16; it++) {
        int s = it & 1;
        if (it + 1 < 16) {
            loadTile(it + 1, s ^ 1);
            CP_COMMIT();
            CP_WAIT(1);
        } else {
            CP_WAIT(0);
        }
        __syncthreads();

        int sa = s * AST, sb = BOFF + s * AST;
        #pragma unroll
        for (int ks = 0; ks < 4; ks++) {
            int kb = ks * 16;
            uint32_t a[4][4], b4[2][4];
            #pragma unroll
            for (int i = 0; i < 4; i++)
                LDSM4(a[i][0], a[i][1], a[i][2], a[i][3],
                      smem_u + (sa + (mb + i * 16 + aRow) * 72 + kb + aCol) * 2);
            #pragma unroll
            for (int jp = 0; jp < 2; jp++)
                LDSM4(b4[jp][0], b4[jp][1], b4[jp][2], b4[jp][3],
                      smem_u + (sb + (nb + jp * 16 + bRow) * 72 + kb + bCol) * 2);
            #pragma unroll
            for (int i = 0; i < 4; i++)
                #pragma unroll
                for (int j = 0; j < 4; j++) {
                    uint32_t bb[2] = { b4[j >> 1][(j & 1) * 2],
                                       b4[j >> 1][(j & 1) * 2 + 1] };
                    MMA_F16(acc[i][j], a[i], bb);
                }
        }
        __syncthreads();
    }

    #pragma unroll
    for (int i = 0; i < 4; i++) {
        int gm = m0 + mb + i * 16 + g;
        #pragma unroll
        for (int j = 0; j < 4; j++) {
            int gn = n0 + nb + j * 8 + tig * 2;
            #pragma unroll
            for (int half_ = 0; half_ < 2; half_++) {
                int m = gm + half_ * 8;
                float v0 = acc[i][j][half_ * 2];
                float v1 = acc[i][j][half_ * 2 + 1];
                if (!QKV) {
                    float* C = (float*)c0;
                    size_t idx = (size_t)m * Dd + gn;
                    float2 xv = *(const float2*)&xres[idx];
                    *(float2*)&C[idx] = make_float2(v0 + b0[gn] + xv.x,
                                                    v1 + b0[gn + 1] + xv.y);
                } else {
                    int bi = m >> 11, s2 = m & (Ss - 1);
                    int hh = gn >> 6, d = gn & 63;
                    if (z < 2) {
                        __half* C = (__half*)((z == 0) ? c0 : c1);
                        uint32_t pv = packh2((v0 + bias[gn]) * osc,
                                             (v1 + bias[gn + 1]) * osc);
                        *(uint32_t*)&C[(((size_t)(bi * Hh + hh) * Ss) + s2) * DK + d] = pv;
                    } else {
                        __half* C = (__half*)c2;
                        size_t base = ((size_t)(bi * Hh + hh) * DK + d) * Ss + s2;
                        C[base]      = __float2half(v0 + bias[gn]);
                        C[base + Ss] = __float2half(v1 + bias[gn + 1]);
                    }
                }
            }
        }
    }
}

// ---------------------------------------------------------------------------
// Fused attention: fp16 mma + ldmatrix, bitmask, no-max softmax, register-P,
// streaming attn stores. Q pre-scaled so p = ex2(s).
// ---------------------------------------------------------------------------
__global__ __launch_bounds__(256, 2) void attn_fused(
    const __half* __restrict__ Q, const __half* __restrict__ Kk,
    const __half* __restrict__ Vt, const uint32_t* __restrict__ mbits,
    float* __restrict__ attn, __half* __restrict__ O)
{
    extern __shared__ __align__(16) __half hsm[];
    float* fsm = (float*)hsm;
    const int KA = 9216, KB = 9216, VB = 18432;
    const int WSS = 13824, SMI = 14336;
    uint32_t smem_u = (uint32_t)__cvta_generic_to_shared(hsm);

    int tid = threadIdx.x;
    int bz = blockIdx.y;               // bh
    int m0 = blockIdx.x * 128;
    const __half* Qp = Q  + (size_t)bz * Ss * DK;
    const __half* Kp = Kk + (size_t)bz * Ss * DK;
    const __half* Vp = Vt + (size_t)bz * DK * Ss;
    const uint32_t* mb_ = mbits + (size_t)(bz >> 4) * Ss * (Ss / 32);
    float* arow = attn + (size_t)bz * Ss * Ss;

    int lane = tid & 31, warp = tid >> 5;
    int wm = warp >> 2, wn = warp & 3;
    int g = lane >> 2, tig = lane & 3;
    int mbA = wm * 64;
    int mbB = warp * 16;

    int aRow = lane & 15;
    int aCol = (lane >> 4) << 3;
    int bRow = ((lane >> 4) << 3) + (lane & 7);
    int bCol = ((lane >> 3) & 1) << 3;

    // ---- load Q strip + first K tile: 128 rows x 64 halves = 1024 chunks ----
    #pragma unroll
    for (int i = 0; i < 4; i++) {
        int idx = tid + i * 256;
        int r = idx >> 3, c = (idx & 7) * 8;
        CP16(smem_u + (r * 72 + c) * 2, Qp + (size_t)(m0 + r) * DK + c);
    }
    #pragma unroll
    for (int i = 0; i < 4; i++) {
        int idx = tid + i * 256;
        int r = idx >> 3, c = (idx & 7) * 8;
        CP16(smem_u + (KA + r * 72 + c) * 2, Kp + (size_t)r * DK + c);
    }
    CP_COMMIT();

    float zs[8];
    #pragma unroll
    for (int s8 = 0; s8 < 8; s8++) zs[s8] = 0.0f;

    // ================= pass A: Z only =================
    for (int kt = 0; kt < 16; kt++) {
        CP_WAIT(0);
        __syncthreads();

        if (kt + 1 < 16) {
            int bo = KA + ((kt + 1) & 1) * 9216;
            #pragma unroll
            for (int i = 0; i < 4; i++) {
                int idx = tid + i * 256;
                int r = idx >> 3, c = (idx & 7) * 8;
                CP16(smem_u + (bo + r * 72 + c) * 2,
                     Kp + (size_t)((kt + 1) * 128 + r) * DK + c);
            }
            CP_COMMIT();
        }

        int ko = KA + (kt & 1) * 9216;
        float acc[4][4][4] = {};
        #pragma unroll
        for (int ks = 0; ks < 4; ks++) {
            int kb = ks * 16;
            uint32_t a[4][4], b4[2][4];
            #pragma unroll
            for (int i = 0; i < 4; i++)
                LDSM4(a[i][0], a[i][1], a[i][2], a[i][3],
                      smem_u + ((mbA + i * 16 + aRow) * 72 + kb + aCol) * 2);
            #pragma unroll
            for (int jp = 0; jp < 2; jp++)
                LDSM4(b4[jp][0], b4[jp][1], b4[jp][2], b4[jp][3],
                      smem_u + (ko + (wn * 32 + jp * 16 + bRow) * 72 + kb + bCol) * 2);
            #pragma unroll
            for (int i = 0; i < 4; i++)
                #pragma unroll
                for (int j = 0; j < 4; j++) {
                    uint32_t bb[2] = { b4[j >> 1][(j & 1) * 2],
                                       b4[j >> 1][(j & 1) * 2 + 1] };
                    MMA_F16(acc[i][j], a[i], bb);
                }
        }

        // epilogue: bitmask exp-sum; Q pre-scaled so exp = ex2(acc)
        #pragma unroll
        for (int i = 0; i < 4; i++) {
            #pragma unroll
            for (int half_ = 0; half_ < 2; half_++) {
                int s8 = i * 2 + half_;
                int m = m0 + mbA + i * 16 + half_ * 8 + g;
                uint32_t bm = mb_[(size_t)m * 64 + kt * 4 + wn];
                float se = 0.0f;
                #pragma unroll
                for (int j = 0; j < 4; j++) {
                    int bp = j * 8 + tig * 2;
                    if ((bm >> bp) & 1)
                        se += ex2f(acc[i][j][half_ * 2]);
                    if ((bm >> (bp + 1)) & 1)
                        se += ex2f(acc[i][j][half_ * 2 + 1]);
                }
                zs[s8] += se;
            }
        }
    }

    // quad-reduce, per-warp partials
    #pragma unroll
    for (int s8 = 0; s8 < 8; s8++) {
        zs[s8] += __shfl_xor_sync(0xffffffffu, zs[s8], 1);
        zs[s8] += __shfl_xor_sync(0xffffffffu, zs[s8], 2);
    }
    if (tig == 0) {
        #pragma unroll
        for (int s8 = 0; s8 < 8; s8++) {
            int rloc = mbA + (s8 >> 1) * 16 + (s8 & 1) * 8 + g;
            fsm[WSS + rloc * 4 + wn] = zs[s8];
        }
    }
    __syncthreads();

    // preload pass-B tile 0
    #pragma unroll
    for (int i = 0; i < 2; i++) {
        int idx = tid + i * 256;
        int r = idx >> 3, c = (idx & 7) * 8;
        CP16(smem_u + (KB + r * 72 + c) * 2, Kp + (size_t)r * DK + c);
        CP16(smem_u + (VB + r * 72 + c) * 2, Vp + (size_t)r * Ss + c);
    }
    CP_COMMIT();

    if (tid < 128) {
        float Z = fsm[WSS + tid * 4] + fsm[WSS + tid * 4 + 1] +
                  fsm[WSS + tid * 4 + 2] + fsm[WSS + tid * 4 + 3];
        fsm[SMI + tid] = 1.0f / Z;
    }
    __syncthreads();

    float invlo = fsm[SMI + mbB + g];
    float invhi = fsm[SMI + mbB + g + 8];

    // ================= pass B =================
    float oacc[8][4] = {};

    for (int tt = 0; tt < 32; tt++) {
        CP_WAIT(0);
        __syncthreads();

        if (tt + 1 < 32) {
            int kbo = KB + ((tt + 1) & 1) * 4608;
            int vbo = VB + ((tt + 1) & 1) * 4608;
            #pragma unroll
            for (int i = 0; i < 2; i++) {
                int idx = tid + i * 256;
                int r = idx >> 3, c = (idx & 7) * 8;
                CP16(smem_u + (kbo + r * 72 + c) * 2,
                     Kp + (size_t)((tt + 1) * 64 + r) * DK + c);
                CP16(smem_u + (vbo + r * 72 + c) * 2,
                     Vp + (size_t)r * Ss + (tt + 1) * 64 + c);
            }
            CP_COMMIT();
        }

        int ko = KB + (tt & 1) * 4608;
        int vo = VB + (tt & 1) * 4608;

        // --- S for all 64 keys, warp-exclusive rows mbB..mbB+15 ---
        float sacc[8][4] = {};
        #pragma unroll
        for (int ks = 0; ks < 4; ks++) {
            int kb = ks * 16;
            uint32_t a[4], b4[4][4];
            LDSM4(a[0], a[1], a[2], a[3],
                  smem_u + ((mbB + aRow) * 72 + kb + aCol) * 2);
            #pragma unroll
            for (int jp = 0; jp < 4; jp++)
                LDSM4(b4[jp][0], b4[jp][1], b4[jp][2], b4[jp][3],
                      smem_u + (ko + (jp * 16 + bRow) * 72 + kb + bCol) * 2);
            #pragma unroll
            for (int j = 0; j < 8; j++) {
                uint32_t bb[2] = { b4[j >> 1][(j & 1) * 2],
                                   b4[j >> 1][(j & 1) * 2 + 1] };
                MMA_F16(sacc[j], a, bb);
            }
        }

        // --- epilogue: p = ex2(s)*invZ via bitmask; streaming attn store ---
        int mlo = m0 + mbB + g, mhi = mlo + 8;
        uint2 bmlo = *(const uint2*)&mb_[(size_t)mlo * 64 + tt * 2];
        uint2 bmhi = *(const uint2*)&mb_[(size_t)mhi * 64 + tt * 2];
        #pragma unroll
        for (int j = 0; j < 8; j++) {
            int gn = tt * 64 + j * 8 + tig * 2;
            size_t i0 = (size_t)mlo * Ss + gn;
            size_t i1 = (size_t)mhi * Ss + gn;
            int sh = (j * 8 + tig * 2) & 31;
            uint32_t wlo = (j < 4) ? bmlo.x : bmlo.y;
            uint32_t whi = (j < 4) ? bmhi.x : bmhi.y;
            float p0 = ((wlo >> sh) & 1)       ? ex2f(sacc[j][0]) * invlo : 0.0f;
            float p1 = ((wlo >> (sh + 1)) & 1) ? ex2f(sacc[j][1]) * invlo : 0.0f;
            float p2 = ((whi >> sh) & 1)       ? ex2f(sacc[j][2]) * invhi : 0.0f;
            float p3 = ((whi >> (sh + 1)) & 1) ? ex2f(sacc[j][3]) * invhi : 0.0f;
            __stcs((float2*)&arow[i0], make_float2(p0, p1));
            __stcs((float2*)&arow[i1], make_float2(p2, p3));
            sacc[j][0] = p0; sacc[j][1] = p1;
            sacc[j][2] = p2; sacc[j][3] = p3;
        }

        // --- AV: pack S-frag -> A-frag in registers; O += P@V ---
        #pragma unroll
        for (int q = 0; q < 4; q++) {
            uint32_t a[4];
            a[0] = packh2(sacc[2 * q][0],     sacc[2 * q][1]);
            a[1] = packh2(sacc[2 * q][2],     sacc[2 * q][3]);
            a[2] = packh2(sacc[2 * q + 1][0], sacc[2 * q + 1][1]);
            a[3] = packh2(sacc[2 * q + 1][2], sacc[2 * q + 1][3]);

            int kb = q * 16;
            uint32_t b4[4][4];
            #pragma unroll
            for (int jp = 0; jp < 4; jp++)
                LDSM4(b4[jp][0], b4[jp][1], b4[jp][2], b4[jp][3],
                      smem_u + (vo + (jp * 16 + bRow) * 72 + kb + bCol) * 2);
            #pragma unroll
            for (int j2 = 0; j2 < 8; j2++) {
                uint32_t bb[2] = { b4[j2 >> 1][(j2 & 1) * 2],
                                   b4[j2 >> 1][(j2 & 1) * 2 + 1] };
                MMA_F16(oacc[j2], a, bb);
            }
        }
    }

    // ---- O epilogue (fp16 O feeds FC) ----
    int bi = bz >> 4, hh = bz & 15;
    int mlo = m0 + mbB + g;
    #pragma unroll
    for (int j2 = 0; j2 < 8; j2++) {
        int d = hh * 64 + j2 * 8 + tig * 2;
        *(uint32_t*)&O[((size_t)bi * Ss + mlo) * Dd + d] =
            packh2(oacc[j2][0], oacc[j2][1]);
        *(uint32_t*)&O[((size_t)bi * Ss + mlo + 8) * Dd + d] =
            packh2(oacc[j2][2], oacc[j2][3]);
    }
}

// ---------------------------------------------------------------------------
extern "C" void kernel_launch(void* const* d_in, const int* in_sizes, int n_in,
                              void* d_out, int out_size)
{
    const float* x    = (const float*)d_in[0];
    const int*   mask = (const int*)d_in[1];
    const float* ln_a = (const float*)d_in[2];
    const float* ln_b = (const float*)d_in[3];
    const float* wq_w = (const float*)d_in[4];
    const float* wq_b = (const float*)d_in[5];
    const float* wk_w = (const float*)d_in[6];
    const float* wk_b = (const float*)d_in[7];
    const float* wv_w = (const float*)d_in[8];
    const float* wv_b = (const float*)d_in[9];
    const float* fc_w = (const float*)d_in[10];
    const float* fc_b = (const float*)d_in[11];
    float* out = (float*)d_out;

    void *ph, *pq, *pk, *pvt, *po, *pwq, *pwk, *pwv, *pwf, *pmb;
    cudaGetSymbolAddress(&ph,  g_h);
    cudaGetSymbolAddress(&pq,  g_q);
    cudaGetSymbolAddress(&pk,  g_k);
    cudaGetSymbolAddress(&pvt, g_vt);
    cudaGetSymbolAddress(&po,  g_o);
    cudaGetSymbolAddress(&pwq, g_wq);
    cudaGetSymbolAddress(&pwk, g_wk);
    cudaGetSymbolAddress(&pwv, g_wv);
    cudaGetSymbolAddress(&pwf, g_wf);
    cudaGetSymbolAddress(&pmb, g_mbits);
    __half* h   = (__half*)ph;
    __half* q   = (__half*)pq;
    __half* k   = (__half*)pk;
    __half* vt  = (__half*)pvt;
    __half* o   = (__half*)po;

    float* attn = out + OUT_ELEMS;

    const int DSM_G = 73728;
    const int DSM_A = 57856;
    cudaFuncSetAttribute(gemm_h<1>, cudaFuncAttributeMaxDynamicSharedMemorySize, DSM_G);
    cudaFuncSetAttribute(gemm_h<0>, cudaFuncAttributeMaxDynamicSharedMemorySize, DSM_G);
    cudaFuncSetAttribute(attn_fused, cudaFuncAttributeMaxDynamicSharedMemorySize, DSM_A);

    // 0a. mask -> bitmap
    mask_bits_kernel<<<(Bb * Ss * (Ss / 32)) / 256, 256>>>(mask, (uint32_t*)pmb);

    // 0b. Weights -> fp16 (one launch)
    whalf4_kernel<<<dim3(1024, 4), 256>>>(
        wq_w, wk_w, wv_w, fc_w,
        (__half*)pwq, (__half*)pwk, (__half*)pwv, (__half*)pwf);

    // 1. LayerNorm (fp16 out)
    ln_kernel<<<Bb * Ss, 256>>>(x, ln_a, ln_b, h);

    // 2. QKV projections (single z-indexed launch; Q pre-scaled by EXP_SC)
    gemm_h<1><<<dim3(8, 64, 3), 256, DSM_G>>>(
        h, (__half*)pwq, (__half*)pwk, (__half*)pwv,
        wq_b, wk_b, wv_b, nullptr, q, k, vt);

    // 3+4+5. Fused attention
    attn_fused<<<dim3(16, Bb * Hh), 256, DSM_A>>>(
        q, k, vt, (const uint32_t*)pmb, attn, o);

    // 6. FC + bias + residual
    gemm_h<0><<<dim3(8, 64, 1), 256, DSM_G>>>(
        o, (__half*)pwf, nullptr, nullptr,
        fc_b, nullptr, nullptr, x, out, nullptr, nullptr);
}

// round 13
// speedup vs baseline: 1.0047x; 1.0047x over previous
#include <cuda_runtime.h>
#include <cuda_fp16.h>
#include <math.h>
#include <stdint.h>

#define Bb 4
#define Ss 2048
#define Dd 1024
#define Hh 16
#define DK 64

static const size_t OUT_ELEMS = (size_t)Bb * Ss * Dd;   // 8388608

// Scratch (device globals — allocation-free per harness rules)
__device__ __half g_h[(size_t)Bb * Ss * Dd];
__device__ __half g_q[(size_t)Bb * Hh * Ss * DK];
__device__ __half g_k[(size_t)Bb * Hh * Ss * DK];
__device__ __half g_vt[(size_t)Bb * Hh * DK * Ss];  // V^T: [bh][d][s]
__device__ __half g_o[(size_t)Bb * Ss * Dd];
__device__ __half g_wq[(size_t)Dd * Dd];
__device__ __half g_wk[(size_t)Dd * Dd];
__device__ __half g_wv[(size_t)Dd * Dd];
__device__ __half g_wf[(size_t)Dd * Dd];
__device__ uint32_t g_mbits[(size_t)Bb * Ss * (Ss / 32)];   // 1 bit / key

// ---------------------------------------------------------------------------
#define CP16(dst_u32, src_ptr) \
    asm volatile("cp.async.cg.shared.global [%0], [%1], 16;\n" :: "r"(dst_u32), "l"(src_ptr))
#define CP_COMMIT() asm volatile("cp.async.commit_group;\n" ::)
#define CP_WAIT(N)  asm volatile("cp.async.wait_group %0;\n" :: "n"(N))

#define MMA_F16(acc, a, b) \
    asm volatile( \
        "mma.sync.aligned.m16n8k16.row.col.f32.f16.f16.f32 " \
        "{%0,%1,%2,%3}, {%4,%5,%6,%7}, {%8,%9}, {%0,%1,%2,%3};" \
        : "+f"(acc[0]), "+f"(acc[1]), "+f"(acc[2]), "+f"(acc[3]) \
        : "r"(a[0]), "r"(a[1]), "r"(a[2]), "r"(a[3]), "r"(b[0]), "r"(b[1]))

#define LDSM4(R0, R1, R2, R3, ADDR) \
    asm volatile("ldmatrix.sync.aligned.m8n8.x4.shared.b16 {%0,%1,%2,%3}, [%4];" \
        : "=r"(R0), "=r"(R1), "=r"(R2), "=r"(R3) : "r"(ADDR))

__device__ __forceinline__ uint32_t packh2(float lo, float hi) {
    __half2 h = __floats2half2_rn(lo, hi);
    return *(uint32_t*)&h;
}
// Q is pre-scaled by 0.125*log2(e), so exp(0.125*s_raw) = ex2(s)
#define EXP_SC 0.1803368801111244f
__device__ __forceinline__ float ex2f(float x) {
    float r;
    asm("ex2.approx.f32 %0, %1;" : "=f"(r) : "f"(x));
    return r;
}

__device__ __forceinline__ float blockReduceSum(float val) {
    __shared__ float sh[32];
    int lane = threadIdx.x & 31, wid = threadIdx.x >> 5;
    #pragma unroll
    for (int o = 16; o; o >>= 1) val += __shfl_down_sync(0xffffffffu, val, o);
    if (lane == 0) sh[wid] = val;
    __syncthreads();
    val = (threadIdx.x < 8) ? sh[lane] : 0.0f;
    if (wid == 0) {
        #pragma unroll
        for (int o = 4; o; o >>= 1) val += __shfl_down_sync(0xffffffffu, val, o);
    }
    __syncthreads();
    return val;
}

// ---------------------------------------------------------------------------
// mask (int32) -> bitmap (1 bit per element), warp-ballot, fully coalesced
// ---------------------------------------------------------------------------
__global__ __launch_bounds__(256) void mask_bits_kernel(
    const int* __restrict__ mask, uint32_t* __restrict__ bits)
{
    int warp = threadIdx.x >> 5, lane = threadIdx.x & 31;
    size_t w0 = (size_t)blockIdx.x * 256 + warp * 32;
    #pragma unroll 4
    for (int i = 0; i < 32; i++) {
        size_t w = w0 + i;
        int v = mask[w * 32 + lane];
        uint32_t bm = __ballot_sync(0xffffffffu, v != 0);
        if (lane == 0) bits[w] = bm;
    }
}

// ---------------------------------------------------------------------------
// LayerNorm — writes fp16 h
// ---------------------------------------------------------------------------
__global__ __launch_bounds__(256) void ln_kernel(
    const float* __restrict__ x, const float* __restrict__ a,
    const float* __restrict__ bvec, __half* __restrict__ h)
{
    int row = blockIdx.x;
    const float4* xr = (const float4*)(x + (size_t)row * Dd);
    float4 v = xr[threadIdx.x];

    float s = blockReduceSum(v.x + v.y + v.z + v.w);
    __shared__ float mean_s, inv_s;
    if (threadIdx.x == 0) mean_s = s * (1.0f / Dd);
    __syncthreads();
    float mean = mean_s;

    float dx = v.x - mean, dy = v.y - mean, dz = v.z - mean, dw = v.w - mean;
    float sq = blockReduceSum(dx * dx + dy * dy + dz * dz + dw * dw);
    if (threadIdx.x == 0) inv_s = 1.0f / (sqrtf(sq * (1.0f / (Dd - 1))) + 1e-6f);
    __syncthreads();
    float inv = inv_s;

    float4 av = ((const float4*)a)[threadIdx.x];
    float4 bv = ((const float4*)bvec)[threadIdx.x];
    uint2 o;
    o.x = packh2(av.x * dx * inv + bv.x, av.y * dy * inv + bv.y);
    o.y = packh2(av.z * dz * inv + bv.z, av.w * dw * inv + bv.w);
    *(uint2*)(h + (size_t)row * Dd + threadIdx.x * 4) = o;
}

// All 4 weights in one launch; blockIdx.y selects the pair.
__global__ __launch_bounds__(256) void whalf4_kernel(
    const float* __restrict__ s0, const float* __restrict__ s1,
    const float* __restrict__ s2, const float* __restrict__ s3,
    __half* __restrict__ d0, __half* __restrict__ d1,
    __half* __restrict__ d2, __half* __restrict__ d3)
{
    int z = blockIdx.y;
    const float* src = (z == 0) ? s0 : (z == 1) ? s1 : (z == 2) ? s2 : s3;
    __half* dst      = (z == 0) ? d0 : (z == 1) ? d1 : (z == 2) ? d2 : d3;
    int i = blockIdx.x * 256 + threadIdx.x;
    float4 v = ((const float4*)src)[i];
    uint2 o;
    o.x = packh2(v.x, v.y);
    o.y = packh2(v.z, v.w);
    *(uint2*)(dst + (size_t)i * 4) = o;
}

// ---------------------------------------------------------------------------
// fp16 GEMM core (ldmatrix fragments). BM=128, BN=128, BK=64, 8 warps.
// Single __syncthreads per k-iteration (prefetch issued after the barrier).
// QKV==1: blockIdx.z selects Q/K/V weight + scatter epilogue (Q pre-scaled).
// QKV==0: FC (+bias+residual, fp32 out).
// ---------------------------------------------------------------------------
template<int QKV>
__global__ __launch_bounds__(256, 2) void gemm_h(
    const __half* __restrict__ A,
    const __half* __restrict__ w0, const __half* __restrict__ w1,
    const __half* __restrict__ w2,
    const float* __restrict__ b0, const float* __restrict__ b1,
    const float* __restrict__ b2,
    const float* __restrict__ xres,
    void* __restrict__ c0, void* __restrict__ c1, void* __restrict__ c2)
{
    extern __shared__ __align__(16) __half hsm[];
    const int AST = 9216, BOFF = 18432;    // half units
    uint32_t smem_u = (uint32_t)__cvta_generic_to_shared(hsm);

    int z = QKV ? blockIdx.z : 0;
    const __half* B    = (z == 0) ? w0 : (z == 1) ? w1 : w2;
    const float* bias  = (z == 0) ? b0 : (z == 1) ? b1 : b2;
    float osc = (QKV && z == 0) ? EXP_SC : 1.0f;   // fold exp scale into Q

    const int K = Dd;
    int tid = threadIdx.x;
    int m0 = blockIdx.y * 128, n0 = blockIdx.x * 128;
    int lane = tid & 31, warp = tid >> 5;
    int wm = warp >> 2, wn = warp & 3;
    int g = lane >> 2, tig = lane & 3;
    int mb = wm * 64, nb = wn * 32;

    int aRow = lane & 15;
    int aCol = (lane >> 4) << 3;
    int bRow = ((lane >> 4) << 3) + (lane & 7);
    int bCol = ((lane >> 3) & 1) << 3;

    float acc[4][4][4] = {};

    int r_ld = tid >> 3;
    int c_ld = (tid & 7) * 8;

    auto loadTile = [&](int kt, int s) {
        int kof = kt * 64;
        #pragma unroll
        for (int i = 0; i < 4; i++) {
            int r = r_ld + i * 32;
            CP16(smem_u + (s * AST + r * 72 + c_ld) * 2,
                 A + (size_t)(m0 + r) * K + kof + c_ld);
        }
        #pragma unroll
        for (int i = 0; i < 4; i++) {
            int r = r_ld + i * 32;
            CP16(smem_u + (BOFF + s * AST + r * 72 + c_ld) * 2,
                 B + (size_t)(n0 + r) * K + kof + c_ld);
        }
    };

    loadTile(0, 0);
    CP_COMMIT();

    for (int it = 0; it < 16; it++) {
        int s = it & 1;
        CP_WAIT(0);
        __syncthreads();            // data for tile it ready; buffer s^1 free

        if (it + 1 < 16) {
            loadTile(it + 1, s ^ 1);
            CP_COMMIT();
        }

        int sa = s * AST, sb = BOFF + s * AST;
        #pragma unroll
        for (int ks = 0; ks < 4; ks++) {
            int kb = ks * 16;
            uint32_t a[4][4], b4[2][4];
            #pragma unroll
            for (int i = 0; i < 4; i++)
                LDSM4(a[i][0], a[i][1], a[i][2], a[i][3],
                      smem_u + (sa + (mb + i * 16 + aRow) * 72 + kb + aCol) * 2);
            #pragma unroll
            for (int jp = 0; jp < 2; jp++)
                LDSM4(b4[jp][0], b4[jp][1], b4[jp][2], b4[jp][3],
                      smem_u + (sb + (nb + jp * 16 + bRow) * 72 + kb + bCol) * 2);
            #pragma unroll
            for (int i = 0; i < 4; i++)
                #pragma unroll
                for (int j = 0; j < 4; j++) {
                    uint32_t bb[2] = { b4[j >> 1][(j & 1) * 2],
                                       b4[j >> 1][(j & 1) * 2 + 1] };
                    MMA_F16(acc[i][j], a[i], bb);
                }
        }
    }

    #pragma unroll
    for (int i = 0; i < 4; i++) {
        int gm = m0 + mb + i * 16 + g;
        #pragma unroll
        for (int j = 0; j < 4; j++) {
            int gn = n0 + nb + j * 8 + tig * 2;
            #pragma unroll
            for (int half_ = 0; half_ < 2; half_++) {
                int m = gm + half_ * 8;
                float v0 = acc[i][j][half_ * 2];
                float v1 = acc[i][j][half_ * 2 + 1];
                if (!QKV) {
                    float* C = (float*)c0;
                    size_t idx = (size_t)m * Dd + gn;
                    float2 xv = *(const float2*)&xres[idx];
                    *(float2*)&C[idx] = make_float2(v0 + b0[gn] + xv.x,
                                                    v1 + b0[gn + 1] + xv.y);
                } else {
                    int bi = m >> 11, s2 = m & (Ss - 1);
                    int hh = gn >> 6, d = gn & 63;
                    if (z < 2) {
                        __half* C = (__half*)((z == 0) ? c0 : c1);
                        uint32_t pv = packh2((v0 + bias[gn]) * osc,
                                             (v1 + bias[gn + 1]) * osc);
                        *(uint32_t*)&C[(((size_t)(bi * Hh + hh) * Ss) + s2) * DK + d] = pv;
                    } else {
                        __half* C = (__half*)c2;
                        size_t base = ((size_t)(bi * Hh + hh) * DK + d) * Ss + s2;
                        C[base]      = __float2half(v0 + bias[gn]);
                        C[base + Ss] = __float2half(v1 + bias[gn + 1]);
                    }
                }
            }
        }
    }
}

// ---------------------------------------------------------------------------
// Fused attention: fp16 mma + ldmatrix, bitmask, no-max softmax, register-P.
// Q pre-scaled so p = ex2(s).
// ---------------------------------------------------------------------------
__global__ __launch_bounds__(256, 2) void attn_fused(
    const __half* __restrict__ Q, const __half* __restrict__ Kk,
    const __half* __restrict__ Vt, const uint32_t* __restrict__ mbits,
    float* __restrict__ attn, __half* __restrict__ O)
{
    extern __shared__ __align__(16) __half hsm[];
    float* fsm = (float*)hsm;
    const int KA = 9216, KB = 9216, VB = 18432;
    const int WSS = 13824, SMI = 14336;
    uint32_t smem_u = (uint32_t)__cvta_generic_to_shared(hsm);

    int tid = threadIdx.x;
    int bz = blockIdx.y;               // bh
    int m0 = blockIdx.x * 128;
    const __half* Qp = Q  + (size_t)bz * Ss * DK;
    const __half* Kp = Kk + (size_t)bz * Ss * DK;
    const __half* Vp = Vt + (size_t)bz * DK * Ss;
    const uint32_t* mb_ = mbits + (size_t)(bz >> 4) * Ss * (Ss / 32);
    float* arow = attn + (size_t)bz * Ss * Ss;

    int lane = tid & 31, warp = tid >> 5;
    int wm = warp >> 2, wn = warp & 3;
    int g = lane >> 2, tig = lane & 3;
    int mbA = wm * 64;
    int mbB = warp * 16;

    int aRow = lane & 15;
    int aCol = (lane >> 4) << 3;
    int bRow = ((lane >> 4) << 3) + (lane & 7);
    int bCol = ((lane >> 3) & 1) << 3;

    // ---- load Q strip + first K tile: 128 rows x 64 halves = 1024 chunks ----
    #pragma unroll
    for (int i = 0; i < 4; i++) {
        int idx = tid + i * 256;
        int r = idx >> 3, c = (idx & 7) * 8;
        CP16(smem_u + (r * 72 + c) * 2, Qp + (size_t)(m0 + r) * DK + c);
    }
    #pragma unroll
    for (int i = 0; i < 4; i++) {
        int idx = tid + i * 256;
        int r = idx >> 3, c = (idx & 7) * 8;
        CP16(smem_u + (KA + r * 72 + c) * 2, Kp + (size_t)r * DK + c);
    }
    CP_COMMIT();

    float zs[8];
    #pragma unroll
    for (int s8 = 0; s8 < 8; s8++) zs[s8] = 0.0f;

    // ================= pass A: Z only =================
    for (int kt = 0; kt < 16; kt++) {
        CP_WAIT(0);
        __syncthreads();

        if (kt + 1 < 16) {
            int bo = KA + ((kt + 1) & 1) * 9216;
            #pragma unroll
            for (int i = 0; i < 4; i++) {
                int idx = tid + i * 256;
                int r = idx >> 3, c = (idx & 7) * 8;
                CP16(smem_u + (bo + r * 72 + c) * 2,
                     Kp + (size_t)((kt + 1) * 128 + r) * DK + c);
            }
            CP_COMMIT();
        }

        int ko = KA + (kt & 1) * 9216;
        float acc[4][4][4] = {};
        #pragma unroll
        for (int ks = 0; ks < 4; ks++) {
            int kb = ks * 16;
            uint32_t a[4][4], b4[2][4];
            #pragma unroll
            for (int i = 0; i < 4; i++)
                LDSM4(a[i][0], a[i][1], a[i][2], a[i][3],
                      smem_u + ((mbA + i * 16 + aRow) * 72 + kb + aCol) * 2);
            #pragma unroll
            for (int jp = 0; jp < 2; jp++)
                LDSM4(b4[jp][0], b4[jp][1], b4[jp][2], b4[jp][3],
                      smem_u + (ko + (wn * 32 + jp * 16 + bRow) * 72 + kb + bCol) * 2);
            #pragma unroll
            for (int i = 0; i < 4; i++)
                #pragma unroll
                for (int j = 0; j < 4; j++) {
                    uint32_t bb[2] = { b4[j >> 1][(j & 1) * 2],
                                       b4[j >> 1][(j & 1) * 2 + 1] };
                    MMA_F16(acc[i][j], a[i], bb);
                }
        }

        // epilogue: bitmask exp-sum; Q pre-scaled so exp = ex2(acc)
        #pragma unroll
        for (int i = 0; i < 4; i++) {
            #pragma unroll
            for (int half_ = 0; half_ < 2; half_++) {
                int s8 = i * 2 + half_;
                int m = m0 + mbA + i * 16 + half_ * 8 + g;
                uint32_t bm = mb_[(size_t)m * 64 + kt * 4 + wn];
                float se = 0.0f;
                #pragma unroll
                for (int j = 0; j < 4; j++) {
                    int bp = j * 8 + tig * 2;
                    if ((bm >> bp) & 1)
                        se += ex2f(acc[i][j][half_ * 2]);
                    if ((bm >> (bp + 1)) & 1)
                        se += ex2f(acc[i][j][half_ * 2 + 1]);
                }
                zs[s8] += se;
            }
        }
    }

    // quad-reduce, per-warp partials
    #pragma unroll
    for (int s8 = 0; s8 < 8; s8++) {
        zs[s8] += __shfl_xor_sync(0xffffffffu, zs[s8], 1);
        zs[s8] += __shfl_xor_sync(0xffffffffu, zs[s8], 2);
    }
    if (tig == 0) {
        #pragma unroll
        for (int s8 = 0; s8 < 8; s8++) {
            int rloc = mbA + (s8 >> 1) * 16 + (s8 & 1) * 8 + g;
            fsm[WSS + rloc * 4 + wn] = zs[s8];
        }
    }
    __syncthreads();

    // preload pass-B tile 0
    #pragma unroll
    for (int i = 0; i < 2; i++) {
        int idx = tid + i * 256;
        int r = idx >> 3, c = (idx & 7) * 8;
        CP16(smem_u + (KB + r * 72 + c) * 2, Kp + (size_t)r * DK + c);
        CP16(smem_u + (VB + r * 72 + c) * 2, Vp + (size_t)r * Ss + c);
    }
    CP_COMMIT();

    if (tid < 128) {
        float Z = fsm[WSS + tid * 4] + fsm[WSS + tid * 4 + 1] +
                  fsm[WSS + tid * 4 + 2] + fsm[WSS + tid * 4 + 3];
        fsm[SMI + tid] = 1.0f / Z;
    }
    __syncthreads();

    float invlo = fsm[SMI + mbB + g];
    float invhi = fsm[SMI + mbB + g + 8];

    // ================= pass B =================
    float oacc[8][4] = {};

    for (int tt = 0; tt < 32; tt++) {
        CP_WAIT(0);
        __syncthreads();

        if (tt + 1 < 32) {
            int kbo = KB + ((tt + 1) & 1) * 4608;
            int vbo = VB + ((tt + 1) & 1) * 4608;
            #pragma unroll
            for (int i = 0; i < 2; i++) {
                int idx = tid + i * 256;
                int r = idx >> 3, c = (idx & 7) * 8;
                CP16(smem_u + (kbo + r * 72 + c) * 2,
                     Kp + (size_t)((tt + 1) * 64 + r) * DK + c);
                CP16(smem_u + (vbo + r * 72 + c) * 2,
                     Vp + (size_t)r * Ss + (tt + 1) * 64 + c);
            }
            CP_COMMIT();
        }

        int ko = KB + (tt & 1) * 4608;
        int vo = VB + (tt & 1) * 4608;

        // --- S for all 64 keys, warp-exclusive rows mbB..mbB+15 ---
        float sacc[8][4] = {};
        #pragma unroll
        for (int ks = 0; ks < 4; ks++) {
            int kb = ks * 16;
            uint32_t a[4], b4[4][4];
            LDSM4(a[0], a[1], a[2], a[3],
                  smem_u + ((mbB + aRow) * 72 + kb + aCol) * 2);
            #pragma unroll
            for (int jp = 0; jp < 4; jp++)
                LDSM4(b4[jp][0], b4[jp][1], b4[jp][2], b4[jp][3],
                      smem_u + (ko + (jp * 16 + bRow) * 72 + kb + bCol) * 2);
            #pragma unroll
            for (int j = 0; j < 8; j++) {
                uint32_t bb[2] = { b4[j >> 1][(j & 1) * 2],
                                   b4[j >> 1][(j & 1) * 2 + 1] };
                MMA_F16(sacc[j], a, bb);
            }
        }

        // --- epilogue: p = ex2(s)*invZ via bitmask; write attn ---
        int mlo = m0 + mbB + g, mhi = mlo + 8;
        uint2 bmlo = *(const uint2*)&mb_[(size_t)mlo * 64 + tt * 2];
        uint2 bmhi = *(const uint2*)&mb_[(size_t)mhi * 64 + tt * 2];
        #pragma unroll
        for (int j = 0; j < 8; j++) {
            int gn = tt * 64 + j * 8 + tig * 2;
            size_t i0 = (size_t)mlo * Ss + gn;
            size_t i1 = (size_t)mhi * Ss + gn;
            int sh = (j * 8 + tig * 2) & 31;
            uint32_t wlo = (j < 4) ? bmlo.x : bmlo.y;
            uint32_t whi = (j < 4) ? bmhi.x : bmhi.y;
            float p0 = ((wlo >> sh) & 1)       ? ex2f(sacc[j][0]) * invlo : 0.0f;
            float p1 = ((wlo >> (sh + 1)) & 1) ? ex2f(sacc[j][1]) * invlo : 0.0f;
            float p2 = ((whi >> sh) & 1)       ? ex2f(sacc[j][2]) * invhi : 0.0f;
            float p3 = ((whi >> (sh + 1)) & 1) ? ex2f(sacc[j][3]) * invhi : 0.0f;
            *(float2*)&arow[i0] = make_float2(p0, p1);
            *(float2*)&arow[i1] = make_float2(p2, p3);
            sacc[j][0] = p0; sacc[j][1] = p1;
            sacc[j][2] = p2; sacc[j][3] = p3;
        }

        // --- AV: pack S-frag -> A-frag in registers; O += P@V ---
        #pragma unroll
        for (int q = 0; q < 4; q++) {
            uint32_t a[4];
            a[0] = packh2(sacc[2 * q][0],     sacc[2 * q][1]);
            a[1] = packh2(sacc[2 * q][2],     sacc[2 * q][3]);
            a[2] = packh2(sacc[2 * q + 1][0], sacc[2 * q + 1][1]);
            a[3] = packh2(sacc[2 * q + 1][2], sacc[2 * q + 1][3]);

            int kb = q * 16;
            uint32_t b4[4][4];
            #pragma unroll
            for (int jp = 0; jp < 4; jp++)
                LDSM4(b4[jp][0], b4[jp][1], b4[jp][2], b4[jp][3],
                      smem_u + (vo + (jp * 16 + bRow) * 72 + kb + bCol) * 2);
            #pragma unroll
            for (int j2 = 0; j2 < 8; j2++) {
                uint32_t bb[2] = { b4[j2 >> 1][(j2 & 1) * 2],
                                   b4[j2 >> 1][(j2 & 1) * 2 + 1] };
                MMA_F16(oacc[j2], a, bb);
            }
        }
    }

    // ---- O epilogue (fp16 O feeds FC) ----
    int bi = bz >> 4, hh = bz & 15;
    int mlo = m0 + mbB + g;
    #pragma unroll
    for (int j2 = 0; j2 < 8; j2++) {
        int d = hh * 64 + j2 * 8 + tig * 2;
        *(uint32_t*)&O[((size_t)bi * Ss + mlo) * Dd + d] =
            packh2(oacc[j2][0], oacc[j2][1]);
        *(uint32_t*)&O[((size_t)bi * Ss + mlo + 8) * Dd + d] =
            packh2(oacc[j2][2], oacc[j2][3]);
    }
}

// ---------------------------------------------------------------------------
extern "C" void kernel_launch(void* const* d_in, const int* in_sizes, int n_in,
                              void* d_out, int out_size)
{
    const float* x    = (const float*)d_in[0];
    const int*   mask = (const int*)d_in[1];
    const float* ln_a = (const float*)d_in[2];
    const float* ln_b = (const float*)d_in[3];
    const float* wq_w = (const float*)d_in[4];
    const float* wq_b = (const float*)d_in[5];
    const float* wk_w = (const float*)d_in[6];
    const float* wk_b = (const float*)d_in[7];
    const float* wv_w = (const float*)d_in[8];
    const float* wv_b = (const float*)d_in[9];
    const float* fc_w = (const float*)d_in[10];
    const float* fc_b = (const float*)d_in[11];
    float* out = (float*)d_out;

    void *ph, *pq, *pk, *pvt, *po, *pwq, *pwk, *pwv, *pwf, *pmb;
    cudaGetSymbolAddress(&ph,  g_h);
    cudaGetSymbolAddress(&pq,  g_q);
    cudaGetSymbolAddress(&pk,  g_k);
    cudaGetSymbolAddress(&pvt, g_vt);
    cudaGetSymbolAddress(&po,  g_o);
    cudaGetSymbolAddress(&pwq, g_wq);
    cudaGetSymbolAddress(&pwk, g_wk);
    cudaGetSymbolAddress(&pwv, g_wv);
    cudaGetSymbolAddress(&pwf, g_wf);
    cudaGetSymbolAddress(&pmb, g_mbits);
    __half* h   = (__half*)ph;
    __half* q   = (__half*)pq;
    __half* k   = (__half*)pk;
    __half* vt  = (__half*)pvt;
    __half* o   = (__half*)po;

    float* attn = out + OUT_ELEMS;

    const int DSM_G = 73728;
    const int DSM_A = 57856;
    cudaFuncSetAttribute(gemm_h<1>, cudaFuncAttributeMaxDynamicSharedMemorySize, DSM_G);
    cudaFuncSetAttribute(gemm_h<0>, cudaFuncAttributeMaxDynamicSharedMemorySize, DSM_G);
    cudaFuncSetAttribute(attn_fused, cudaFuncAttributeMaxDynamicSharedMemorySize, DSM_A);

    // 0a. mask -> bitmap
    mask_bits_kernel<<<(Bb * Ss * (Ss / 32)) / 256, 256>>>(mask, (uint32_t*)pmb);

    // 0b. Weights -> fp16 (one launch)
    whalf4_kernel<<<dim3(1024, 4), 256>>>(
        wq_w, wk_w, wv_w, fc_w,
        (__half*)pwq, (__half*)pwk, (__half*)pwv, (__half*)pwf);

    // 1. LayerNorm (fp16 out)
    ln_kernel<<<Bb * Ss, 256>>>(x, ln_a, ln_b, h);

    // 2. QKV projections (single z-indexed launch; Q pre-scaled by EXP_SC)
    gemm_h<1><<<dim3(8, 64, 3), 256, DSM_G>>>(
        h, (__half*)pwq, (__half*)pwk, (__half*)pwv,
        wq_b, wk_b, wv_b, nullptr, q, k, vt);

    // 3+4+5. Fused attention
    attn_fused<<<dim3(16, Bb * Hh), 256, DSM_A>>>(
        q, k, vt, (const uint32_t*)pmb, attn, o);

    // 6. FC + bias + residual
    gemm_h<0><<<dim3(8, 64, 1), 256, DSM_G>>>(
        o, (__half*)pwf, nullptr, nullptr,
        fc_b, nullptr, nullptr, x, out, nullptr, nullptr);
}

// round 14
// speedup vs baseline: 1.0458x; 1.0409x over previous
#include <cuda_runtime.h>
#include <cuda_fp16.h>
#include <math.h>
#include <stdint.h>

#define Bb 4
#define Ss 2048
#define Dd 1024
#define Hh 16
#define DK 64

static const size_t OUT_ELEMS = (size_t)Bb * Ss * Dd;   // 8388608

// Scratch (device globals — allocation-free per harness rules)
__device__ __half g_h[(size_t)Bb * Ss * Dd];
__device__ __half g_q[(size_t)Bb * Hh * Ss * DK];
__device__ __half g_k[(size_t)Bb * Hh * Ss * DK];
__device__ __half g_vt[(size_t)Bb * Hh * DK * Ss];  // V^T: [bh][d][s]
__device__ __half g_o[(size_t)Bb * Ss * Dd];
__device__ __half g_wq[(size_t)Dd * Dd];
__device__ __half g_wk[(size_t)Dd * Dd];
__device__ __half g_wv[(size_t)Dd * Dd];
__device__ __half g_wf[(size_t)Dd * Dd];
__device__ uint32_t g_mbits[(size_t)Bb * Ss * (Ss / 32)];   // 1 bit / key

// ---------------------------------------------------------------------------
#define CP16(dst_u32, src_ptr) \
    asm volatile("cp.async.cg.shared.global [%0], [%1], 16;\n" :: "r"(dst_u32), "l"(src_ptr))
#define CP_COMMIT() asm volatile("cp.async.commit_group;\n" ::)
#define CP_WAIT(N)  asm volatile("cp.async.wait_group %0;\n" :: "n"(N))

#define MMA_F16(acc, a, b) \
    asm volatile( \
        "mma.sync.aligned.m16n8k16.row.col.f32.f16.f16.f32 " \
        "{%0,%1,%2,%3}, {%4,%5,%6,%7}, {%8,%9}, {%0,%1,%2,%3};" \
        : "+f"(acc[0]), "+f"(acc[1]), "+f"(acc[2]), "+f"(acc[3]) \
        : "r"(a[0]), "r"(a[1]), "r"(a[2]), "r"(a[3]), "r"(b[0]), "r"(b[1]))

#define LDSM4(R0, R1, R2, R3, ADDR) \
    asm volatile("ldmatrix.sync.aligned.m8n8.x4.shared.b16 {%0,%1,%2,%3}, [%4];" \
        : "=r"(R0), "=r"(R1), "=r"(R2), "=r"(R3) : "r"(ADDR))

__device__ __forceinline__ uint32_t packh2(float lo, float hi) {
    __half2 h = __floats2half2_rn(lo, hi);
    return *(uint32_t*)&h;
}
// Q is pre-scaled by 0.125*log2(e), so exp(0.125*s_raw) = ex2(s)
#define EXP_SC 0.1803368801111244f
__device__ __forceinline__ float ex2f(float x) {
    float r;
    asm("ex2.approx.f32 %0, %1;" : "=f"(r) : "f"(x));
    return r;
}

__device__ __forceinline__ float blockReduceSum(float val) {
    __shared__ float sh[32];
    int lane = threadIdx.x & 31, wid = threadIdx.x >> 5;
    #pragma unroll
    for (int o = 16; o; o >>= 1) val += __shfl_down_sync(0xffffffffu, val, o);
    if (lane == 0) sh[wid] = val;
    __syncthreads();
    val = (threadIdx.x < 8) ? sh[lane] : 0.0f;
    if (wid == 0) {
        #pragma unroll
        for (int o = 4; o; o >>= 1) val += __shfl_down_sync(0xffffffffu, val, o);
    }
    __syncthreads();
    return val;
}

// ---------------------------------------------------------------------------
// mask (int32) -> bitmap (1 bit per element), warp-ballot, fully coalesced
// ---------------------------------------------------------------------------
__global__ __launch_bounds__(256) void mask_bits_kernel(
    const int* __restrict__ mask, uint32_t* __restrict__ bits)
{
    int warp = threadIdx.x >> 5, lane = threadIdx.x & 31;
    size_t w0 = (size_t)blockIdx.x * 256 + warp * 32;
    #pragma unroll 4
    for (int i = 0; i < 32; i++) {
        size_t w = w0 + i;
        int v = mask[w * 32 + lane];
        uint32_t bm = __ballot_sync(0xffffffffu, v != 0);
        if (lane == 0) bits[w] = bm;
    }
}

// ---------------------------------------------------------------------------
// LayerNorm — writes fp16 h
// ---------------------------------------------------------------------------
__global__ __launch_bounds__(256) void ln_kernel(
    const float* __restrict__ x, const float* __restrict__ a,
    const float* __restrict__ bvec, __half* __restrict__ h)
{
    int row = blockIdx.x;
    const float4* xr = (const float4*)(x + (size_t)row * Dd);
    float4 v = xr[threadIdx.x];

    float s = blockReduceSum(v.x + v.y + v.z + v.w);
    __shared__ float mean_s, inv_s;
    if (threadIdx.x == 0) mean_s = s * (1.0f / Dd);
    __syncthreads();
    float mean = mean_s;

    float dx = v.x - mean, dy = v.y - mean, dz = v.z - mean, dw = v.w - mean;
    float sq = blockReduceSum(dx * dx + dy * dy + dz * dz + dw * dw);
    if (threadIdx.x == 0) inv_s = 1.0f / (sqrtf(sq * (1.0f / (Dd - 1))) + 1e-6f);
    __syncthreads();
    float inv = inv_s;

    float4 av = ((const float4*)a)[threadIdx.x];
    float4 bv = ((const float4*)bvec)[threadIdx.x];
    uint2 o;
    o.x = packh2(av.x * dx * inv + bv.x, av.y * dy * inv + bv.y);
    o.y = packh2(av.z * dz * inv + bv.z, av.w * dw * inv + bv.w);
    *(uint2*)(h + (size_t)row * Dd + threadIdx.x * 4) = o;
}

// All 4 weights in one launch; blockIdx.y selects the pair.
__global__ __launch_bounds__(256) void whalf4_kernel(
    const float* __restrict__ s0, const float* __restrict__ s1,
    const float* __restrict__ s2, const float* __restrict__ s3,
    __half* __restrict__ d0, __half* __restrict__ d1,
    __half* __restrict__ d2, __half* __restrict__ d3)
{
    int z = blockIdx.y;
    const float* src = (z == 0) ? s0 : (z == 1) ? s1 : (z == 2) ? s2 : s3;
    __half* dst      = (z == 0) ? d0 : (z == 1) ? d1 : (z == 2) ? d2 : d3;
    int i = blockIdx.x * 256 + threadIdx.x;
    float4 v = ((const float4*)src)[i];
    uint2 o;
    o.x = packh2(v.x, v.y);
    o.y = packh2(v.z, v.w);
    *(uint2*)(dst + (size_t)i * 4) = o;
}

// ---------------------------------------------------------------------------
// fp16 GEMM core (ldmatrix fragments). BM=128, BN=128, BK=64, 8 warps.
// QKV==1: blockIdx.z selects Q/K/V weight + scatter epilogue (Q pre-scaled).
// QKV==0: FC (+bias+residual, fp32 out).
// ---------------------------------------------------------------------------
template<int QKV>
__global__ __launch_bounds__(256, 2) void gemm_h(
    const __half* __restrict__ A,
    const __half* __restrict__ w0, const __half* __restrict__ w1,
    const __half* __restrict__ w2,
    const float* __restrict__ b0, const float* __restrict__ b1,
    const float* __restrict__ b2,
    const float* __restrict__ xres,
    void* __restrict__ c0, void* __restrict__ c1, void* __restrict__ c2)
{
    extern __shared__ __align__(16) __half hsm[];
    const int AST = 9216, BOFF = 18432;    // half units
    uint32_t smem_u = (uint32_t)__cvta_generic_to_shared(hsm);

    int z = QKV ? blockIdx.z : 0;
    const __half* B    = (z == 0) ? w0 : (z == 1) ? w1 : w2;
    const float* bias  = (z == 0) ? b0 : (z == 1) ? b1 : b2;
    float osc = (QKV && z == 0) ? EXP_SC : 1.0f;   // fold exp scale into Q

    const int K = Dd;
    int tid = threadIdx.x;
    int m0 = blockIdx.y * 128, n0 = blockIdx.x * 128;
    int lane = tid & 31, warp = tid >> 5;
    int wm = warp >> 2, wn = warp & 3;
    int g = lane >> 2, tig = lane & 3;
    int mb = wm * 64, nb = wn * 32;

    int aRow = lane & 15;
    int aCol = (lane >> 4) << 3;
    int bRow = ((lane >> 4) << 3) + (lane & 7);
    int bCol = ((lane >> 3) & 1) << 3;

    float acc[4][4][4] = {};

    int r_ld = tid >> 3;
    int c_ld = (tid & 7) * 8;

    auto loadTile = [&](int kt, int s) {
        int kof = kt * 64;
        #pragma unroll
        for (int i = 0; i < 4; i++) {
            int r = r_ld + i * 32;
            CP16(smem_u + (s * AST + r * 72 + c_ld) * 2,
                 A + (size_t)(m0 + r) * K + kof + c_ld);
        }
        #pragma unroll
        for (int i = 0; i < 4; i++) {
            int r = r_ld + i * 32;
            CP16(smem_u + (BOFF + s * AST + r * 72 + c_ld) * 2,
                 B + (size_t)(n0 + r) * K + kof + c_ld);
        }
    };

    loadTile(0, 0);
    CP_COMMIT();

    for (int it = 0; it < 16; it++) {
        int s = it & 1;
        CP_WAIT(0);
        __syncthreads();

        if (it + 1 < 16) {
            loadTile(it + 1, s ^ 1);
            CP_COMMIT();
        }

        int sa = s * AST, sb = BOFF + s * AST;
        #pragma unroll
        for (int ks = 0; ks < 4; ks++) {
            int kb = ks * 16;
            uint32_t a[4][4], b4[2][4];
            #pragma unroll
            for (int i = 0; i < 4; i++)
                LDSM4(a[i][0], a[i][1], a[i][2], a[i][3],
                      smem_u + (sa + (mb + i * 16 + aRow) * 72 + kb + aCol) * 2);
            #pragma unroll
            for (int jp = 0; jp < 2; jp++)
                LDSM4(b4[jp][0], b4[jp][1], b4[jp][2], b4[jp][3],
                      smem_u + (sb + (nb + jp * 16 + bRow) * 72 + kb + bCol) * 2);
            #pragma unroll
            for (int i = 0; i < 4; i++)
                #pragma unroll
                for (int j = 0; j < 4; j++) {
                    uint32_t bb[2] = { b4[j >> 1][(j & 1) * 2],
                                       b4[j >> 1][(j & 1) * 2 + 1] };
                    MMA_F16(acc[i][j], a[i], bb);
                }
        }
    }

    #pragma unroll
    for (int i = 0; i < 4; i++) {
        int gm = m0 + mb + i * 16 + g;
        #pragma unroll
        for (int j = 0; j < 4; j++) {
            int gn = n0 + nb + j * 8 + tig * 2;
            #pragma unroll
            for (int half_ = 0; half_ < 2; half_++) {
                int m = gm + half_ * 8;
                float v0 = acc[i][j][half_ * 2];
                float v1 = acc[i][j][half_ * 2 + 1];
                if (!QKV) {
                    float* C = (float*)c0;
                    size_t idx = (size_t)m * Dd + gn;
                    float2 xv = *(const float2*)&xres[idx];
                    *(float2*)&C[idx] = make_float2(v0 + b0[gn] + xv.x,
                                                    v1 + b0[gn + 1] + xv.y);
                } else {
                    int bi = m >> 11, s2 = m & (Ss - 1);
                    int hh = gn >> 6, d = gn & 63;
                    if (z < 2) {
                        __half* C = (__half*)((z == 0) ? c0 : c1);
                        uint32_t pv = packh2((v0 + bias[gn]) * osc,
                                             (v1 + bias[gn + 1]) * osc);
                        *(uint32_t*)&C[(((size_t)(bi * Hh + hh) * Ss) + s2) * DK + d] = pv;
                    } else {
                        __half* C = (__half*)c2;
                        size_t base = ((size_t)(bi * Hh + hh) * DK + d) * Ss + s2;
                        C[base]      = __float2half(v0 + bias[gn]);
                        C[base + Ss] = __float2half(v1 + bias[gn + 1]);
                    }
                }
            }
        }
    }
}

// ---------------------------------------------------------------------------
// Fused attention: fp16 mma + ldmatrix, bitmask with all-ones fast path,
// no-max softmax, register-P. Q pre-scaled so p = ex2(s).
// ---------------------------------------------------------------------------
__global__ __launch_bounds__(256, 2) void attn_fused(
    const __half* __restrict__ Q, const __half* __restrict__ Kk,
    const __half* __restrict__ Vt, const uint32_t* __restrict__ mbits,
    float* __restrict__ attn, __half* __restrict__ O)
{
    extern __shared__ __align__(16) __half hsm[];
    float* fsm = (float*)hsm;
    const int KA = 9216, KB = 9216, VB = 18432;
    const int WSS = 13824, SMI = 14336;
    uint32_t smem_u = (uint32_t)__cvta_generic_to_shared(hsm);

    int tid = threadIdx.x;
    int bz = blockIdx.y;               // bh
    int m0 = blockIdx.x * 128;
    const __half* Qp = Q  + (size_t)bz * Ss * DK;
    const __half* Kp = Kk + (size_t)bz * Ss * DK;
    const __half* Vp = Vt + (size_t)bz * DK * Ss;
    const uint32_t* mb_ = mbits + (size_t)(bz >> 4) * Ss * (Ss / 32);
    float* arow = attn + (size_t)bz * Ss * Ss;

    int lane = tid & 31, warp = tid >> 5;
    int wm = warp >> 2, wn = warp & 3;
    int g = lane >> 2, tig = lane & 3;
    int mbA = wm * 64;
    int mbB = warp * 16;

    int aRow = lane & 15;
    int aCol = (lane >> 4) << 3;
    int bRow = ((lane >> 4) << 3) + (lane & 7);
    int bCol = ((lane >> 3) & 1) << 3;

    // ---- load Q strip + first K tile ----
    #pragma unroll
    for (int i = 0; i < 4; i++) {
        int idx = tid + i * 256;
        int r = idx >> 3, c = (idx & 7) * 8;
        CP16(smem_u + (r * 72 + c) * 2, Qp + (size_t)(m0 + r) * DK + c);
    }
    #pragma unroll
    for (int i = 0; i < 4; i++) {
        int idx = tid + i * 256;
        int r = idx >> 3, c = (idx & 7) * 8;
        CP16(smem_u + (KA + r * 72 + c) * 2, Kp + (size_t)r * DK + c);
    }
    CP_COMMIT();

    float zs[8];
    #pragma unroll
    for (int s8 = 0; s8 < 8; s8++) zs[s8] = 0.0f;

    // ================= pass A: Z only =================
    for (int kt = 0; kt < 16; kt++) {
        CP_WAIT(0);
        __syncthreads();

        if (kt + 1 < 16) {
            int bo = KA + ((kt + 1) & 1) * 9216;
            #pragma unroll
            for (int i = 0; i < 4; i++) {
                int idx = tid + i * 256;
                int r = idx >> 3, c = (idx & 7) * 8;
                CP16(smem_u + (bo + r * 72 + c) * 2,
                     Kp + (size_t)((kt + 1) * 128 + r) * DK + c);
            }
            CP_COMMIT();
        }

        int ko = KA + (kt & 1) * 9216;
        float acc[4][4][4] = {};
        #pragma unroll
        for (int ks = 0; ks < 4; ks++) {
            int kb = ks * 16;
            uint32_t a[4][4], b4[2][4];
            #pragma unroll
            for (int i = 0; i < 4; i++)
                LDSM4(a[i][0], a[i][1], a[i][2], a[i][3],
                      smem_u + ((mbA + i * 16 + aRow) * 72 + kb + aCol) * 2);
            #pragma unroll
            for (int jp = 0; jp < 2; jp++)
                LDSM4(b4[jp][0], b4[jp][1], b4[jp][2], b4[jp][3],
                      smem_u + (ko + (wn * 32 + jp * 16 + bRow) * 72 + kb + bCol) * 2);
            #pragma unroll
            for (int i = 0; i < 4; i++)
                #pragma unroll
                for (int j = 0; j < 4; j++) {
                    uint32_t bb[2] = { b4[j >> 1][(j & 1) * 2],
                                       b4[j >> 1][(j & 1) * 2 + 1] };
                    MMA_F16(acc[i][j], a[i], bb);
                }
        }

        // epilogue: exp-sum with all-ones fast path (no per-element tests)
        #pragma unroll
        for (int i = 0; i < 4; i++) {
            #pragma unroll
            for (int half_ = 0; half_ < 2; half_++) {
                int s8 = i * 2 + half_;
                int m = m0 + mbA + i * 16 + half_ * 8 + g;
                uint32_t bm = mb_[(size_t)m * 64 + kt * 4 + wn];
                float se = 0.0f;
                if (bm == 0xffffffffu) {
                    #pragma unroll
                    for (int j = 0; j < 4; j++) {
                        se += ex2f(acc[i][j][half_ * 2]);
                        se += ex2f(acc[i][j][half_ * 2 + 1]);
                    }
                } else {
                    #pragma unroll
                    for (int j = 0; j < 4; j++) {
                        int bp = j * 8 + tig * 2;
                        if ((bm >> bp) & 1)
                            se += ex2f(acc[i][j][half_ * 2]);
                        if ((bm >> (bp + 1)) & 1)
                            se += ex2f(acc[i][j][half_ * 2 + 1]);
                    }
                }
                zs[s8] += se;
            }
        }
    }

    // quad-reduce, per-warp partials
    #pragma unroll
    for (int s8 = 0; s8 < 8; s8++) {
        zs[s8] += __shfl_xor_sync(0xffffffffu, zs[s8], 1);
        zs[s8] += __shfl_xor_sync(0xffffffffu, zs[s8], 2);
    }
    if (tig == 0) {
        #pragma unroll
        for (int s8 = 0; s8 < 8; s8++) {
            int rloc = mbA + (s8 >> 1) * 16 + (s8 & 1) * 8 + g;
            fsm[WSS + rloc * 4 + wn] = zs[s8];
        }
    }
    __syncthreads();

    // preload pass-B tile 0
    #pragma unroll
    for (int i = 0; i < 2; i++) {
        int idx = tid + i * 256;
        int r = idx >> 3, c = (idx & 7) * 8;
        CP16(smem_u + (KB + r * 72 + c) * 2, Kp + (size_t)r * DK + c);
        CP16(smem_u + (VB + r * 72 + c) * 2, Vp + (size_t)r * Ss + c);
    }
    CP_COMMIT();

    if (tid < 128) {
        float Z = fsm[WSS + tid * 4] + fsm[WSS + tid * 4 + 1] +
                  fsm[WSS + tid * 4 + 2] + fsm[WSS + tid * 4 + 3];
        fsm[SMI + tid] = 1.0f / Z;
    }
    __syncthreads();

    float invlo = fsm[SMI + mbB + g];
    float invhi = fsm[SMI + mbB + g + 8];

    // ================= pass B =================
    float oacc[8][4] = {};

    for (int tt = 0; tt < 32; tt++) {
        CP_WAIT(0);
        __syncthreads();

        if (tt + 1 < 32) {
            int kbo = KB + ((tt + 1) & 1) * 4608;
            int vbo = VB + ((tt + 1) & 1) * 4608;
            #pragma unroll
            for (int i = 0; i < 2; i++) {
                int idx = tid + i * 256;
                int r = idx >> 3, c = (idx & 7) * 8;
                CP16(smem_u + (kbo + r * 72 + c) * 2,
                     Kp + (size_t)((tt + 1) * 64 + r) * DK + c);
                CP16(smem_u + (vbo + r * 72 + c) * 2,
                     Vp + (size_t)r * Ss + (tt + 1) * 64 + c);
            }
            CP_COMMIT();
        }

        int ko = KB + (tt & 1) * 4608;
        int vo = VB + (tt & 1) * 4608;

        // --- S for all 64 keys, warp-exclusive rows mbB..mbB+15 ---
        float sacc[8][4] = {};
        #pragma unroll
        for (int ks = 0; ks < 4; ks++) {
            int kb = ks * 16;
            uint32_t a[4], b4[4][4];
            LDSM4(a[0], a[1], a[2], a[3],
                  smem_u + ((mbB + aRow) * 72 + kb + aCol) * 2);
            #pragma unroll
            for (int jp = 0; jp < 4; jp++)
                LDSM4(b4[jp][0], b4[jp][1], b4[jp][2], b4[jp][3],
                      smem_u + (ko + (jp * 16 + bRow) * 72 + kb + bCol) * 2);
            #pragma unroll
            for (int j = 0; j < 8; j++) {
                uint32_t bb[2] = { b4[j >> 1][(j & 1) * 2],
                                   b4[j >> 1][(j & 1) * 2 + 1] };
                MMA_F16(sacc[j], a, bb);
            }
        }

        // --- epilogue: p = ex2(s)*invZ; all-ones fast path; write attn ---
        int mlo = m0 + mbB + g, mhi = mlo + 8;
        uint2 bmlo = *(const uint2*)&mb_[(size_t)mlo * 64 + tt * 2];
        uint2 bmhi = *(const uint2*)&mb_[(size_t)mhi * 64 + tt * 2];
        bool allones = (bmlo.x & bmlo.y & bmhi.x & bmhi.y) == 0xffffffffu;
        if (allones) {
            #pragma unroll
            for (int j = 0; j < 8; j++) {
                int gn = tt * 64 + j * 8 + tig * 2;
                size_t i0 = (size_t)mlo * Ss + gn;
                size_t i1 = (size_t)mhi * Ss + gn;
                float p0 = ex2f(sacc[j][0]) * invlo;
                float p1 = ex2f(sacc[j][1]) * invlo;
                float p2 = ex2f(sacc[j][2]) * invhi;
                float p3 = ex2f(sacc[j][3]) * invhi;
                *(float2*)&arow[i0] = make_float2(p0, p1);
                *(float2*)&arow[i1] = make_float2(p2, p3);
                sacc[j][0] = p0; sacc[j][1] = p1;
                sacc[j][2] = p2; sacc[j][3] = p3;
            }
        } else {
            #pragma unroll
            for (int j = 0; j < 8; j++) {
                int gn = tt * 64 + j * 8 + tig * 2;
                size_t i0 = (size_t)mlo * Ss + gn;
                size_t i1 = (size_t)mhi * Ss + gn;
                int sh = (j * 8 + tig * 2) & 31;
                uint32_t wlo = (j < 4) ? bmlo.x : bmlo.y;
                uint32_t whi = (j < 4) ? bmhi.x : bmhi.y;
                float p0 = ((wlo >> sh) & 1)       ? ex2f(sacc[j][0]) * invlo : 0.0f;
                float p1 = ((wlo >> (sh + 1)) & 1) ? ex2f(sacc[j][1]) * invlo : 0.0f;
                float p2 = ((whi >> sh) & 1)       ? ex2f(sacc[j][2]) * invhi : 0.0f;
                float p3 = ((whi >> (sh + 1)) & 1) ? ex2f(sacc[j][3]) * invhi : 0.0f;
                *(float2*)&arow[i0] = make_float2(p0, p1);
                *(float2*)&arow[i1] = make_float2(p2, p3);
                sacc[j][0] = p0; sacc[j][1] = p1;
                sacc[j][2] = p2; sacc[j][3] = p3;
            }
        }

        // --- AV: pack S-frag -> A-frag in registers; O += P@V ---
        #pragma unroll
        for (int q = 0; q < 4; q++) {
            uint32_t a[4];
            a[0] = packh2(sacc[2 * q][0],     sacc[2 * q][1]);
            a[1] = packh2(sacc[2 * q][2],     sacc[2 * q][3]);
            a[2] = packh2(sacc[2 * q + 1][0], sacc[2 * q + 1][1]);
            a[3] = packh2(sacc[2 * q + 1][2], sacc[2 * q + 1][3]);

            int kb = q * 16;
            uint32_t b4[4][4];
            #pragma unroll
            for (int jp = 0; jp < 4; jp++)
                LDSM4(b4[jp][0], b4[jp][1], b4[jp][2], b4[jp][3],
                      smem_u + (vo + (jp * 16 + bRow) * 72 + kb + bCol) * 2);
            #pragma unroll
            for (int j2 = 0; j2 < 8; j2++) {
                uint32_t bb[2] = { b4[j2 >> 1][(j2 & 1) * 2],
                                   b4[j2 >> 1][(j2 & 1) * 2 + 1] };
                MMA_F16(oacc[j2], a, bb);
            }
        }
    }

    // ---- O epilogue (fp16 O feeds FC) ----
    int bi = bz >> 4, hh = bz & 15;
    int mlo = m0 + mbB + g;
    #pragma unroll
    for (int j2 = 0; j2 < 8; j2++) {
        int d = hh * 64 + j2 * 8 + tig * 2;
        *(uint32_t*)&O[((size_t)bi * Ss + mlo) * Dd + d] =
            packh2(oacc[j2][0], oacc[j2][1]);
        *(uint32_t*)&O[((size_t)bi * Ss + mlo + 8) * Dd + d] =
            packh2(oacc[j2][2], oacc[j2][3]);
    }
}

// ---------------------------------------------------------------------------
extern "C" void kernel_launch(void* const* d_in, const int* in_sizes, int n_in,
                              void* d_out, int out_size)
{
    const float* x    = (const float*)d_in[0];
    const int*   mask = (const int*)d_in[1];
    const float* ln_a = (const float*)d_in[2];
    const float* ln_b = (const float*)d_in[3];
    const float* wq_w = (const float*)d_in[4];
    const float* wq_b = (const float*)d_in[5];
    const float* wk_w = (const float*)d_in[6];
    const float* wk_b = (const float*)d_in[7];
    const float* wv_w = (const float*)d_in[8];
    const float* wv_b = (const float*)d_in[9];
    const float* fc_w = (const float*)d_in[10];
    const float* fc_b = (const float*)d_in[11];
    float* out = (float*)d_out;

    void *ph, *pq, *pk, *pvt, *po, *pwq, *pwk, *pwv, *pwf, *pmb;
    cudaGetSymbolAddress(&ph,  g_h);
    cudaGetSymbolAddress(&pq,  g_q);
    cudaGetSymbolAddress(&pk,  g_k);
    cudaGetSymbolAddress(&pvt, g_vt);
    cudaGetSymbolAddress(&po,  g_o);
    cudaGetSymbolAddress(&pwq, g_wq);
    cudaGetSymbolAddress(&pwk, g_wk);
    cudaGetSymbolAddress(&pwv, g_wv);
    cudaGetSymbolAddress(&pwf, g_wf);
    cudaGetSymbolAddress(&pmb, g_mbits);
    __half* h   = (__half*)ph;
    __half* q   = (__half*)pq;
    __half* k   = (__half*)pk;
    __half* vt  = (__half*)pvt;
    __half* o   = (__half*)po;

    float* attn = out + OUT_ELEMS;

    const int DSM_G = 73728;
    const int DSM_A = 57856;
    cudaFuncSetAttribute(gemm_h<1>, cudaFuncAttributeMaxDynamicSharedMemorySize, DSM_G);
    cudaFuncSetAttribute(gemm_h<0>, cudaFuncAttributeMaxDynamicSharedMemorySize, DSM_G);
    cudaFuncSetAttribute(attn_fused, cudaFuncAttributeMaxDynamicSharedMemorySize, DSM_A);

    // 0a. mask -> bitmap
    mask_bits_kernel<<<(Bb * Ss * (Ss / 32)) / 256, 256>>>(mask, (uint32_t*)pmb);

    // 0b. Weights -> fp16 (one launch)
    whalf4_kernel<<<dim3(1024, 4), 256>>>(
        wq_w, wk_w, wv_w, fc_w,
        (__half*)pwq, (__half*)pwk, (__half*)pwv, (__half*)pwf);

    // 1. LayerNorm (fp16 out)
    ln_kernel<<<Bb * Ss, 256>>>(x, ln_a, ln_b, h);

    // 2. QKV projections (single z-indexed launch; Q pre-scaled by EXP_SC)
    gemm_h<1><<<dim3(8, 64, 3), 256, DSM_G>>>(
        h, (__half*)pwq, (__half*)pwk, (__half*)pwv,
        wq_b, wk_b, wv_b, nullptr, q, k, vt);

    // 3+4+5. Fused attention
    attn_fused<<<dim3(16, Bb * Hh), 256, DSM_A>>>(
        q, k, vt, (const uint32_t*)pmb, attn, o);

    // 6. FC + bias + residual
    gemm_h<0><<<dim3(8, 64, 1), 256, DSM_G>>>(
        o, (__half*)pwf, nullptr, nullptr,
        fc_b, nullptr, nullptr, x, out, nullptr, nullptr);
}

// round 15
// speedup vs baseline: 1.0692x; 1.0223x over previous
#include <cuda_runtime.h>
#include <cuda_fp16.h>
#include <math.h>
#include <stdint.h>

#define Bb 4
#define Ss 2048
#define Dd 1024
#define Hh 16
#define DK 64

static const size_t OUT_ELEMS = (size_t)Bb * Ss * Dd;   // 8388608

// Scratch (device globals — allocation-free per harness rules)
__device__ __half g_h[(size_t)Bb * Ss * Dd];
__device__ __half g_q[(size_t)Bb * Hh * Ss * DK];
__device__ __half g_k[(size_t)Bb * Hh * Ss * DK];
__device__ __half g_vt[(size_t)Bb * Hh * DK * Ss];  // V^T: [bh][d][s]
__device__ __half g_o[(size_t)Bb * Ss * Dd];
__device__ __half g_wq[(size_t)Dd * Dd];
__device__ __half g_wk[(size_t)Dd * Dd];
__device__ __half g_wv[(size_t)Dd * Dd];
__device__ __half g_wf[(size_t)Dd * Dd];
__device__ uint32_t g_mbits[(size_t)Bb * Ss * (Ss / 32)];   // 1 bit / key

// ---------------------------------------------------------------------------
#define CP16(dst_u32, src_ptr) \
    asm volatile("cp.async.cg.shared.global [%0], [%1], 16;\n" :: "r"(dst_u32), "l"(src_ptr))
#define CP_COMMIT() asm volatile("cp.async.commit_group;\n" ::)
#define CP_WAIT(N)  asm volatile("cp.async.wait_group %0;\n" :: "n"(N))

#define MMA_F16(acc, a, b) \
    asm volatile( \
        "mma.sync.aligned.m16n8k16.row.col.f32.f16.f16.f32 " \
        "{%0,%1,%2,%3}, {%4,%5,%6,%7}, {%8,%9}, {%0,%1,%2,%3};" \
        : "+f"(acc[0]), "+f"(acc[1]), "+f"(acc[2]), "+f"(acc[3]) \
        : "r"(a[0]), "r"(a[1]), "r"(a[2]), "r"(a[3]), "r"(b[0]), "r"(b[1]))

#define LDSM4(R0, R1, R2, R3, ADDR) \
    asm volatile("ldmatrix.sync.aligned.m8n8.x4.shared.b16 {%0,%1,%2,%3}, [%4];" \
        : "=r"(R0), "=r"(R1), "=r"(R2), "=r"(R3) : "r"(ADDR))

__device__ __forceinline__ uint32_t packh2(float lo, float hi) {
    __half2 h = __floats2half2_rn(lo, hi);
    return *(uint32_t*)&h;
}
// Q is pre-scaled by 0.125*log2(e), so exp(0.125*s_raw) = ex2(s)
#define EXP_SC 0.1803368801111244f
__device__ __forceinline__ float ex2f(float x) {
    float r;
    asm("ex2.approx.f32 %0, %1;" : "=f"(r) : "f"(x));
    return r;
}
__device__ __forceinline__ uint32_t h2ex2(uint32_t x) {
    uint32_t r;
    asm("ex2.approx.f16x2 %0, %1;" : "=r"(r) : "r"(x));
    return r;
}
__device__ __forceinline__ float2 h2f2(uint32_t x) {
    __half2 h = *(__half2*)&x;
    return __half22float2(h);
}

__device__ __forceinline__ float blockReduceSum(float val) {
    __shared__ float sh[32];
    int lane = threadIdx.x & 31, wid = threadIdx.x >> 5;
    #pragma unroll
    for (int o = 16; o; o >>= 1) val += __shfl_down_sync(0xffffffffu, val, o);
    if (lane == 0) sh[wid] = val;
    __syncthreads();
    val = (threadIdx.x < 8) ? sh[lane] : 0.0f;
    if (wid == 0) {
        #pragma unroll
        for (int o = 4; o; o >>= 1) val += __shfl_down_sync(0xffffffffu, val, o);
    }
    __syncthreads();
    return val;
}

// ---------------------------------------------------------------------------
// mask (int32) -> bitmap (1 bit per element), warp-ballot, fully coalesced
// ---------------------------------------------------------------------------
__global__ __launch_bounds__(256) void mask_bits_kernel(
    const int* __restrict__ mask, uint32_t* __restrict__ bits)
{
    int warp = threadIdx.x >> 5, lane = threadIdx.x & 31;
    size_t w0 = (size_t)blockIdx.x * 256 + warp * 32;
    #pragma unroll 4
    for (int i = 0; i < 32; i++) {
        size_t w = w0 + i;
        int v = mask[w * 32 + lane];
        uint32_t bm = __ballot_sync(0xffffffffu, v != 0);
        if (lane == 0) bits[w] = bm;
    }
}

// ---------------------------------------------------------------------------
// LayerNorm — writes fp16 h
// ---------------------------------------------------------------------------
__global__ __launch_bounds__(256) void ln_kernel(
    const float* __restrict__ x, const float* __restrict__ a,
    const float* __restrict__ bvec, __half* __restrict__ h)
{
    int row = blockIdx.x;
    const float4* xr = (const float4*)(x + (size_t)row * Dd);
    float4 v = xr[threadIdx.x];

    float s = blockReduceSum(v.x + v.y + v.z + v.w);
    __shared__ float mean_s, inv_s;
    if (threadIdx.x == 0) mean_s = s * (1.0f / Dd);
    __syncthreads();
    float mean = mean_s;

    float dx = v.x - mean, dy = v.y - mean, dz = v.z - mean, dw = v.w - mean;
    float sq = blockReduceSum(dx * dx + dy * dy + dz * dz + dw * dw);
    if (threadIdx.x == 0) inv_s = 1.0f / (sqrtf(sq * (1.0f / (Dd - 1))) + 1e-6f);
    __syncthreads();
    float inv = inv_s;

    float4 av = ((const float4*)a)[threadIdx.x];
    float4 bv = ((const float4*)bvec)[threadIdx.x];
    uint2 o;
    o.x = packh2(av.x * dx * inv + bv.x, av.y * dy * inv + bv.y);
    o.y = packh2(av.z * dz * inv + bv.z, av.w * dw * inv + bv.w);
    *(uint2*)(h + (size_t)row * Dd + threadIdx.x * 4) = o;
}

// All 4 weights in one launch; blockIdx.y selects the pair.
__global__ __launch_bounds__(256) void whalf4_kernel(
    const float* __restrict__ s0, const float* __restrict__ s1,
    const float* __restrict__ s2, const float* __restrict__ s3,
    __half* __restrict__ d0, __half* __restrict__ d1,
    __half* __restrict__ d2, __half* __restrict__ d3)
{
    int z = blockIdx.y;
    const float* src = (z == 0) ? s0 : (z == 1) ? s1 : (z == 2) ? s2 : s3;
    __half* dst      = (z == 0) ? d0 : (z == 1) ? d1 : (z == 2) ? d2 : d3;
    int i = blockIdx.x * 256 + threadIdx.x;
    float4 v = ((const float4*)src)[i];
    uint2 o;
    o.x = packh2(v.x, v.y);
    o.y = packh2(v.z, v.w);
    *(uint2*)(dst + (size_t)i * 4) = o;
}

// ---------------------------------------------------------------------------
// fp16 GEMM core (ldmatrix fragments). BM=128, BN=128, BK=64, 8 warps.
// QKV==1: blockIdx.z selects Q/K/V weight + scatter epilogue (Q pre-scaled).
// QKV==0: FC (+bias+residual, fp32 out).
// ---------------------------------------------------------------------------
template<int QKV>
__global__ __launch_bounds__(256, 2) void gemm_h(
    const __half* __restrict__ A,
    const __half* __restrict__ w0, const __half* __restrict__ w1,
    const __half* __restrict__ w2,
    const float* __restrict__ b0, const float* __restrict__ b1,
    const float* __restrict__ b2,
    const float* __restrict__ xres,
    void* __restrict__ c0, void* __restrict__ c1, void* __restrict__ c2)
{
    extern __shared__ __align__(16) __half hsm[];
    const int AST = 9216, BOFF = 18432;    // half units
    uint32_t smem_u = (uint32_t)__cvta_generic_to_shared(hsm);

    int z = QKV ? blockIdx.z : 0;
    const __half* B    = (z == 0) ? w0 : (z == 1) ? w1 : w2;
    const float* bias  = (z == 0) ? b0 : (z == 1) ? b1 : b2;
    float osc = (QKV && z == 0) ? EXP_SC : 1.0f;   // fold exp scale into Q

    const int K = Dd;
    int tid = threadIdx.x;
    int m0 = blockIdx.y * 128, n0 = blockIdx.x * 128;
    int lane = tid & 31, warp = tid >> 5;
    int wm = warp >> 2, wn = warp & 3;
    int g = lane >> 2, tig = lane & 3;
    int mb = wm * 64, nb = wn * 32;

    int aRow = lane & 15;
    int aCol = (lane >> 4) << 3;
    int bRow = ((lane >> 4) << 3) + (lane & 7);
    int bCol = ((lane >> 3) & 1) << 3;

    float acc[4][4][4] = {};

    int r_ld = tid >> 3;
    int c_ld = (tid & 7) * 8;

    auto loadTile = [&](int kt, int s) {
        int kof = kt * 64;
        #pragma unroll
        for (int i = 0; i < 4; i++) {
            int r = r_ld + i * 32;
            CP16(smem_u + (s * AST + r * 72 + c_ld) * 2,
                 A + (size_t)(m0 + r) * K + kof + c_ld);
        }
        #pragma unroll
        for (int i = 0; i < 4; i++) {
            int r = r_ld + i * 32;
            CP16(smem_u + (BOFF + s * AST + r * 72 + c_ld) * 2,
                 B + (size_t)(n0 + r) * K + kof + c_ld);
        }
    };

    loadTile(0, 0);
    CP_COMMIT();

    for (int it = 0; it < 16; it++) {
        int s = it & 1;
        CP_WAIT(0);
        __syncthreads();

        if (it + 1 < 16) {
            loadTile(it + 1, s ^ 1);
            CP_COMMIT();
        }

        int sa = s * AST, sb = BOFF + s * AST;
        #pragma unroll
        for (int ks = 0; ks < 4; ks++) {
            int kb = ks * 16;
            uint32_t a[4][4], b4[2][4];
            #pragma unroll
            for (int i = 0; i < 4; i++)
                LDSM4(a[i][0], a[i][1], a[i][2], a[i][3],
                      smem_u + (sa + (mb + i * 16 + aRow) * 72 + kb + aCol) * 2);
            #pragma unroll
            for (int jp = 0; jp < 2; jp++)
                LDSM4(b4[jp][0], b4[jp][1], b4[jp][2], b4[jp][3],
                      smem_u + (sb + (nb + jp * 16 + bRow) * 72 + kb + bCol) * 2);
            #pragma unroll
            for (int i = 0; i < 4; i++)
                #pragma unroll
                for (int j = 0; j < 4; j++) {
                    uint32_t bb[2] = { b4[j >> 1][(j & 1) * 2],
                                       b4[j >> 1][(j & 1) * 2 + 1] };
                    MMA_F16(acc[i][j], a[i], bb);
                }
        }
    }

    #pragma unroll
    for (int i = 0; i < 4; i++) {
        int gm = m0 + mb + i * 16 + g;
        #pragma unroll
        for (int j = 0; j < 4; j++) {
            int gn = n0 + nb + j * 8 + tig * 2;
            #pragma unroll
            for (int half_ = 0; half_ < 2; half_++) {
                int m = gm + half_ * 8;
                float v0 = acc[i][j][half_ * 2];
                float v1 = acc[i][j][half_ * 2 + 1];
                if (!QKV) {
                    float* C = (float*)c0;
                    size_t idx = (size_t)m * Dd + gn;
                    float2 xv = *(const float2*)&xres[idx];
                    *(float2*)&C[idx] = make_float2(v0 + b0[gn] + xv.x,
                                                    v1 + b0[gn + 1] + xv.y);
                } else {
                    int bi = m >> 11, s2 = m & (Ss - 1);
                    int hh = gn >> 6, d = gn & 63;
                    if (z < 2) {
                        __half* C = (__half*)((z == 0) ? c0 : c1);
                        uint32_t pv = packh2((v0 + bias[gn]) * osc,
                                             (v1 + bias[gn + 1]) * osc);
                        *(uint32_t*)&C[(((size_t)(bi * Hh + hh) * Ss) + s2) * DK + d] = pv;
                    } else {
                        __half* C = (__half*)c2;
                        size_t base = ((size_t)(bi * Hh + hh) * DK + d) * Ss + s2;
                        C[base]      = __float2half(v0 + bias[gn]);
                        C[base + Ss] = __float2half(v1 + bias[gn + 1]);
                    }
                }
            }
        }
    }
}

// ---------------------------------------------------------------------------
// Fused attention: fp16 mma + ldmatrix, bitmask fast path, no-max softmax,
// f16x2 ex2 (half the MUFU ops), unnormalized AV with end-scaling.
// ---------------------------------------------------------------------------
__global__ __launch_bounds__(256, 2) void attn_fused(
    const __half* __restrict__ Q, const __half* __restrict__ Kk,
    const __half* __restrict__ Vt, const uint32_t* __restrict__ mbits,
    float* __restrict__ attn, __half* __restrict__ O)
{
    extern __shared__ __align__(16) __half hsm[];
    float* fsm = (float*)hsm;
    const int KA = 9216, KB = 9216, VB = 18432;
    const int WSS = 13824, SMI = 14336;
    uint32_t smem_u = (uint32_t)__cvta_generic_to_shared(hsm);

    int tid = threadIdx.x;
    int bz = blockIdx.y;               // bh
    int m0 = blockIdx.x * 128;
    const __half* Qp = Q  + (size_t)bz * Ss * DK;
    const __half* Kp = Kk + (size_t)bz * Ss * DK;
    const __half* Vp = Vt + (size_t)bz * DK * Ss;
    const uint32_t* mb_ = mbits + (size_t)(bz >> 4) * Ss * (Ss / 32);
    float* arow = attn + (size_t)bz * Ss * Ss;

    int lane = tid & 31, warp = tid >> 5;
    int wm = warp >> 2, wn = warp & 3;
    int g = lane >> 2, tig = lane & 3;
    int mbA = wm * 64;
    int mbB = warp * 16;

    int aRow = lane & 15;
    int aCol = (lane >> 4) << 3;
    int bRow = ((lane >> 4) << 3) + (lane & 7);
    int bCol = ((lane >> 3) & 1) << 3;

    // ---- load Q strip + first K tile ----
    #pragma unroll
    for (int i = 0; i < 4; i++) {
        int idx = tid + i * 256;
        int r = idx >> 3, c = (idx & 7) * 8;
        CP16(smem_u + (r * 72 + c) * 2, Qp + (size_t)(m0 + r) * DK + c);
    }
    #pragma unroll
    for (int i = 0; i < 4; i++) {
        int idx = tid + i * 256;
        int r = idx >> 3, c = (idx & 7) * 8;
        CP16(smem_u + (KA + r * 72 + c) * 2, Kp + (size_t)r * DK + c);
    }
    CP_COMMIT();

    float zs[8];
    #pragma unroll
    for (int s8 = 0; s8 < 8; s8++) zs[s8] = 0.0f;

    // ================= pass A: Z only =================
    for (int kt = 0; kt < 16; kt++) {
        CP_WAIT(0);
        __syncthreads();

        if (kt + 1 < 16) {
            int bo = KA + ((kt + 1) & 1) * 9216;
            #pragma unroll
            for (int i = 0; i < 4; i++) {
                int idx = tid + i * 256;
                int r = idx >> 3, c = (idx & 7) * 8;
                CP16(smem_u + (bo + r * 72 + c) * 2,
                     Kp + (size_t)((kt + 1) * 128 + r) * DK + c);
            }
            CP_COMMIT();
        }

        int ko = KA + (kt & 1) * 9216;
        float acc[4][4][4] = {};
        #pragma unroll
        for (int ks = 0; ks < 4; ks++) {
            int kb = ks * 16;
            uint32_t a[4][4], b4[2][4];
            #pragma unroll
            for (int i = 0; i < 4; i++)
                LDSM4(a[i][0], a[i][1], a[i][2], a[i][3],
                      smem_u + ((mbA + i * 16 + aRow) * 72 + kb + aCol) * 2);
            #pragma unroll
            for (int jp = 0; jp < 2; jp++)
                LDSM4(b4[jp][0], b4[jp][1], b4[jp][2], b4[jp][3],
                      smem_u + (ko + (wn * 32 + jp * 16 + bRow) * 72 + kb + bCol) * 2);
            #pragma unroll
            for (int i = 0; i < 4; i++)
                #pragma unroll
                for (int j = 0; j < 4; j++) {
                    uint32_t bb[2] = { b4[j >> 1][(j & 1) * 2],
                                       b4[j >> 1][(j & 1) * 2 + 1] };
                    MMA_F16(acc[i][j], a[i], bb);
                }
        }

        // epilogue: exp-sum; f16x2 ex2 fast path
        #pragma unroll
        for (int i = 0; i < 4; i++) {
            #pragma unroll
            for (int half_ = 0; half_ < 2; half_++) {
                int s8 = i * 2 + half_;
                int m = m0 + mbA + i * 16 + half_ * 8 + g;
                uint32_t bm = mb_[(size_t)m * 64 + kt * 4 + wn];
                float se = 0.0f;
                if (bm == 0xffffffffu) {
                    #pragma unroll
                    for (int j = 0; j < 4; j++) {
                        float2 pf = h2f2(h2ex2(packh2(acc[i][j][half_ * 2],
                                                      acc[i][j][half_ * 2 + 1])));
                        se += pf.x + pf.y;
                    }
                } else {
                    #pragma unroll
                    for (int j = 0; j < 4; j++) {
                        int bp = j * 8 + tig * 2;
                        if ((bm >> bp) & 1)
                            se += ex2f(acc[i][j][half_ * 2]);
                        if ((bm >> (bp + 1)) & 1)
                            se += ex2f(acc[i][j][half_ * 2 + 1]);
                    }
                }
                zs[s8] += se;
            }
        }
    }

    // quad-reduce, per-warp partials
    #pragma unroll
    for (int s8 = 0; s8 < 8; s8++) {
        zs[s8] += __shfl_xor_sync(0xffffffffu, zs[s8], 1);
        zs[s8] += __shfl_xor_sync(0xffffffffu, zs[s8], 2);
    }
    if (tig == 0) {
        #pragma unroll
        for (int s8 = 0; s8 < 8; s8++) {
            int rloc = mbA + (s8 >> 1) * 16 + (s8 & 1) * 8 + g;
            fsm[WSS + rloc * 4 + wn] = zs[s8];
        }
    }
    __syncthreads();

    // preload pass-B tile 0
    #pragma unroll
    for (int i = 0; i < 2; i++) {
        int idx = tid + i * 256;
        int r = idx >> 3, c = (idx & 7) * 8;
        CP16(smem_u + (KB + r * 72 + c) * 2, Kp + (size_t)r * DK + c);
        CP16(smem_u + (VB + r * 72 + c) * 2, Vp + (size_t)r * Ss + c);
    }
    CP_COMMIT();

    if (tid < 128) {
        float Z = fsm[WSS + tid * 4] + fsm[WSS + tid * 4 + 1] +
                  fsm[WSS + tid * 4 + 2] + fsm[WSS + tid * 4 + 3];
        fsm[SMI + tid] = 1.0f / Z;
    }
    __syncthreads();

    float invlo = fsm[SMI + mbB + g];
    float invhi = fsm[SMI + mbB + g + 8];

    // ================= pass B =================
    float oacc[8][4] = {};

    for (int tt = 0; tt < 32; tt++) {
        CP_WAIT(0);
        __syncthreads();

        if (tt + 1 < 32) {
            int kbo = KB + ((tt + 1) & 1) * 4608;
            int vbo = VB + ((tt + 1) & 1) * 4608;
            #pragma unroll
            for (int i = 0; i < 2; i++) {
                int idx = tid + i * 256;
                int r = idx >> 3, c = (idx & 7) * 8;
                CP16(smem_u + (kbo + r * 72 + c) * 2,
                     Kp + (size_t)((tt + 1) * 64 + r) * DK + c);
                CP16(smem_u + (vbo + r * 72 + c) * 2,
                     Vp + (size_t)r * Ss + (tt + 1) * 64 + c);
            }
            CP_COMMIT();
        }

        int ko = KB + (tt & 1) * 4608;
        int vo = VB + (tt & 1) * 4608;

        // --- S for all 64 keys, warp-exclusive rows mbB..mbB+15 ---
        float sacc[8][4] = {};
        #pragma unroll
        for (int ks = 0; ks < 4; ks++) {
            int kb = ks * 16;
            uint32_t a[4], b4[4][4];
            LDSM4(a[0], a[1], a[2], a[3],
                  smem_u + ((mbB + aRow) * 72 + kb + aCol) * 2);
            #pragma unroll
            for (int jp = 0; jp < 4; jp++)
                LDSM4(b4[jp][0], b4[jp][1], b4[jp][2], b4[jp][3],
                      smem_u + (ko + (jp * 16 + bRow) * 72 + kb + bCol) * 2);
            #pragma unroll
            for (int j = 0; j < 8; j++) {
                uint32_t bb[2] = { b4[j >> 1][(j & 1) * 2],
                                   b4[j >> 1][(j & 1) * 2 + 1] };
                MMA_F16(sacc[j], a, bb);
            }
        }

        // --- epilogue: unnormalized p via f16x2 ex2; store normalized ---
        uint32_t pA[8][2];   // f16x2 unnormalized p (AV A-operands)
        int mlo = m0 + mbB + g, mhi = mlo + 8;
        uint2 bmlo = *(const uint2*)&mb_[(size_t)mlo * 64 + tt * 2];
        uint2 bmhi = *(const uint2*)&mb_[(size_t)mhi * 64 + tt * 2];
        bool allones = (bmlo.x & bmlo.y & bmhi.x & bmhi.y) == 0xffffffffu;
        if (allones) {
            #pragma unroll
            for (int j = 0; j < 8; j++) {
                int gn = tt * 64 + j * 8 + tig * 2;
                size_t i0 = (size_t)mlo * Ss + gn;
                size_t i1 = (size_t)mhi * Ss + gn;
                uint32_t plo = h2ex2(packh2(sacc[j][0], sacc[j][1]));
                uint32_t phi = h2ex2(packh2(sacc[j][2], sacc[j][3]));
                float2 flo = h2f2(plo);
                float2 fhi = h2f2(phi);
                *(float2*)&arow[i0] = make_float2(flo.x * invlo, flo.y * invlo);
                *(float2*)&arow[i1] = make_float2(fhi.x * invhi, fhi.y * invhi);
                pA[j][0] = plo;
                pA[j][1] = phi;
            }
        } else {
            #pragma unroll
            for (int j = 0; j < 8; j++) {
                int gn = tt * 64 + j * 8 + tig * 2;
                size_t i0 = (size_t)mlo * Ss + gn;
                size_t i1 = (size_t)mhi * Ss + gn;
                int sh = (j * 8 + tig * 2) & 31;
                uint32_t wlo = (j < 4) ? bmlo.x : bmlo.y;
                uint32_t whi = (j < 4) ? bmhi.x : bmhi.y;
                float p0 = ((wlo >> sh) & 1)       ? ex2f(sacc[j][0]) : 0.0f;
                float p1 = ((wlo >> (sh + 1)) & 1) ? ex2f(sacc[j][1]) : 0.0f;
                float p2 = ((whi >> sh) & 1)       ? ex2f(sacc[j][2]) : 0.0f;
                float p3 = ((whi >> (sh + 1)) & 1) ? ex2f(sacc[j][3]) : 0.0f;
                *(float2*)&arow[i0] = make_float2(p0 * invlo, p1 * invlo);
                *(float2*)&arow[i1] = make_float2(p2 * invhi, p3 * invhi);
                pA[j][0] = packh2(p0, p1);
                pA[j][1] = packh2(p2, p3);
            }
        }

        // --- AV with unnormalized p (scaled at the end) ---
        #pragma unroll
        for (int q = 0; q < 4; q++) {
            uint32_t a[4];
            a[0] = pA[2 * q][0];
            a[1] = pA[2 * q][1];
            a[2] = pA[2 * q + 1][0];
            a[3] = pA[2 * q + 1][1];

            int kb = q * 16;
            uint32_t b4[4][4];
            #pragma unroll
            for (int jp = 0; jp < 4; jp++)
                LDSM4(b4[jp][0], b4[jp][1], b4[jp][2], b4[jp][3],
                      smem_u + (vo + (jp * 16 + bRow) * 72 + kb + bCol) * 2);
            #pragma unroll
            for (int j2 = 0; j2 < 8; j2++) {
                uint32_t bb[2] = { b4[j2 >> 1][(j2 & 1) * 2],
                                   b4[j2 >> 1][(j2 & 1) * 2 + 1] };
                MMA_F16(oacc[j2], a, bb);
            }
        }
    }

    // ---- O epilogue: scale by invZ here (fp16 O feeds FC) ----
    int bi = bz >> 4, hh = bz & 15;
    int mlo = m0 + mbB + g;
    #pragma unroll
    for (int j2 = 0; j2 < 8; j2++) {
        int d = hh * 64 + j2 * 8 + tig * 2;
        *(uint32_t*)&O[((size_t)bi * Ss + mlo) * Dd + d] =
            packh2(oacc[j2][0] * invlo, oacc[j2][1] * invlo);
        *(uint32_t*)&O[((size_t)bi * Ss + mlo + 8) * Dd + d] =
            packh2(oacc[j2][2] * invhi, oacc[j2][3] * invhi);
    }
}

// ---------------------------------------------------------------------------
extern "C" void kernel_launch(void* const* d_in, const int* in_sizes, int n_in,
                              void* d_out, int out_size)
{
    const float* x    = (const float*)d_in[0];
    const int*   mask = (const int*)d_in[1];
    const float* ln_a = (const float*)d_in[2];
    const float* ln_b = (const float*)d_in[3];
    const float* wq_w = (const float*)d_in[4];
    const float* wq_b = (const float*)d_in[5];
    const float* wk_w = (const float*)d_in[6];
    const float* wk_b = (const float*)d_in[7];
    const float* wv_w = (const float*)d_in[8];
    const float* wv_b = (const float*)d_in[9];
    const float* fc_w = (const float*)d_in[10];
    const float* fc_b = (const float*)d_in[11];
    float* out = (float*)d_out;

    void *ph, *pq, *pk, *pvt, *po, *pwq, *pwk, *pwv, *pwf, *pmb;
    cudaGetSymbolAddress(&ph,  g_h);
    cudaGetSymbolAddress(&pq,  g_q);
    cudaGetSymbolAddress(&pk,  g_k);
    cudaGetSymbolAddress(&pvt, g_vt);
    cudaGetSymbolAddress(&po,  g_o);
    cudaGetSymbolAddress(&pwq, g_wq);
    cudaGetSymbolAddress(&pwk, g_wk);
    cudaGetSymbolAddress(&pwv, g_wv);
    cudaGetSymbolAddress(&pwf, g_wf);
    cudaGetSymbolAddress(&pmb, g_mbits);
    __half* h   = (__half*)ph;
    __half* q   = (__half*)pq;
    __half* k   = (__half*)pk;
    __half* vt  = (__half*)pvt;
    __half* o   = (__half*)po;

    float* attn = out + OUT_ELEMS;

    const int DSM_G = 73728;
    const int DSM_A = 57856;
    cudaFuncSetAttribute(gemm_h<1>, cudaFuncAttributeMaxDynamicSharedMemorySize, DSM_G);
    cudaFuncSetAttribute(gemm_h<0>, cudaFuncAttributeMaxDynamicSharedMemorySize, DSM_G);
    cudaFuncSetAttribute(attn_fused, cudaFuncAttributeMaxDynamicSharedMemorySize, DSM_A);

    // 0a. mask -> bitmap
    mask_bits_kernel<<<(Bb * Ss * (Ss / 32)) / 256, 256>>>(mask, (uint32_t*)pmb);

    // 0b. Weights -> fp16 (one launch)
    whalf4_kernel<<<dim3(1024, 4), 256>>>(
        wq_w, wk_w, wv_w, fc_w,
        (__half*)pwq, (__half*)pwk, (__half*)pwv, (__half*)pwf);

    // 1. LayerNorm (fp16 out)
    ln_kernel<<<Bb * Ss, 256>>>(x, ln_a, ln_b, h);

    // 2. QKV projections (single z-indexed launch; Q pre-scaled by EXP_SC)
    gemm_h<1><<<dim3(8, 64, 3), 256, DSM_G>>>(
        h, (__half*)pwq, (__half*)pwk, (__half*)pwv,
        wq_b, wk_b, wv_b, nullptr, q, k, vt);

    // 3+4+5. Fused attention
    attn_fused<<<dim3(16, Bb * Hh), 256, DSM_A>>>(
        q, k, vt, (const uint32_t*)pmb, attn, o);

    // 6. FC + bias + residual
    gemm_h<0><<<dim3(8, 64, 1), 256, DSM_G>>>(
        o, (__half*)pwf, nullptr, nullptr,
        fc_b, nullptr, nullptr, x, out, nullptr, nullptr);
}

// round 16
// speedup vs baseline: 1.0758x; 1.0063x over previous
#include <cuda_runtime.h>
#include <cuda_fp16.h>
#include <math.h>
#include <stdint.h>

#define Bb 4
#define Ss 2048
#define Dd 1024
#define Hh 16
#define DK 64

static const size_t OUT_ELEMS = (size_t)Bb * Ss * Dd;   // 8388608

// Scratch (device globals — allocation-free per harness rules)
__device__ __half g_h[(size_t)Bb * Ss * Dd];
__device__ __half g_q[(size_t)Bb * Hh * Ss * DK];
__device__ __half g_k[(size_t)Bb * Hh * Ss * DK];
__device__ __half g_vt[(size_t)Bb * Hh * DK * Ss];  // V^T: [bh][d][s]
__device__ __half g_o[(size_t)Bb * Ss * Dd];
__device__ __half g_wq[(size_t)Dd * Dd];
__device__ __half g_wk[(size_t)Dd * Dd];
__device__ __half g_wv[(size_t)Dd * Dd];
__device__ __half g_wf[(size_t)Dd * Dd];
__device__ uint32_t g_mbits[(size_t)Bb * Ss * (Ss / 32)];   // 1 bit / key

// ---------------------------------------------------------------------------
#define CP16(dst_u32, src_ptr) \
    asm volatile("cp.async.cg.shared.global [%0], [%1], 16;\n" :: "r"(dst_u32), "l"(src_ptr))
#define CP_COMMIT() asm volatile("cp.async.commit_group;\n" ::)
#define CP_WAIT(N)  asm volatile("cp.async.wait_group %0;\n" :: "n"(N))

#define MMA_F16(acc, a, b) \
    asm volatile( \
        "mma.sync.aligned.m16n8k16.row.col.f32.f16.f16.f32 " \
        "{%0,%1,%2,%3}, {%4,%5,%6,%7}, {%8,%9}, {%0,%1,%2,%3};" \
        : "+f"(acc[0]), "+f"(acc[1]), "+f"(acc[2]), "+f"(acc[3]) \
        : "r"(a[0]), "r"(a[1]), "r"(a[2]), "r"(a[3]), "r"(b[0]), "r"(b[1]))

#define LDSM4(R0, R1, R2, R3, ADDR) \
    asm volatile("ldmatrix.sync.aligned.m8n8.x4.shared.b16 {%0,%1,%2,%3}, [%4];" \
        : "=r"(R0), "=r"(R1), "=r"(R2), "=r"(R3) : "r"(ADDR))

__device__ __forceinline__ uint32_t packh2(float lo, float hi) {
    __half2 h = __floats2half2_rn(lo, hi);
    return *(uint32_t*)&h;
}
// Q is pre-scaled by 0.125*log2(e), so exp(0.125*s_raw) = ex2(s)
#define EXP_SC 0.1803368801111244f
__device__ __forceinline__ float ex2f(float x) {
    float r;
    asm("ex2.approx.f32 %0, %1;" : "=f"(r) : "f"(x));
    return r;
}
__device__ __forceinline__ uint32_t h2ex2(uint32_t x) {
    uint32_t r;
    asm("ex2.approx.f16x2 %0, %1;" : "=r"(r) : "r"(x));
    return r;
}
__device__ __forceinline__ float2 h2f2(uint32_t x) {
    __half2 h = *(__half2*)&x;
    return __half22float2(h);
}

__device__ __forceinline__ float blockReduceSum(float val) {
    __shared__ float sh[32];
    int lane = threadIdx.x & 31, wid = threadIdx.x >> 5;
    #pragma unroll
    for (int o = 16; o; o >>= 1) val += __shfl_down_sync(0xffffffffu, val, o);
    if (lane == 0) sh[wid] = val;
    __syncthreads();
    val = (threadIdx.x < 8) ? sh[lane] : 0.0f;
    if (wid == 0) {
        #pragma unroll
        for (int o = 4; o; o >>= 1) val += __shfl_down_sync(0xffffffffu, val, o);
    }
    __syncthreads();
    return val;
}

// ---------------------------------------------------------------------------
// mask (int32) -> bitmap (1 bit per element), warp-ballot, fully coalesced
// ---------------------------------------------------------------------------
__global__ __launch_bounds__(256) void mask_bits_kernel(
    const int* __restrict__ mask, uint32_t* __restrict__ bits)
{
    int warp = threadIdx.x >> 5, lane = threadIdx.x & 31;
    size_t w0 = (size_t)blockIdx.x * 256 + warp * 32;
    #pragma unroll 4
    for (int i = 0; i < 32; i++) {
        size_t w = w0 + i;
        int v = mask[w * 32 + lane];
        uint32_t bm = __ballot_sync(0xffffffffu, v != 0);
        if (lane == 0) bits[w] = bm;
    }
}

// ---------------------------------------------------------------------------
// LayerNorm — writes fp16 h
// ---------------------------------------------------------------------------
__global__ __launch_bounds__(256) void ln_kernel(
    const float* __restrict__ x, const float* __restrict__ a,
    const float* __restrict__ bvec, __half* __restrict__ h)
{
    int row = blockIdx.x;
    const float4* xr = (const float4*)(x + (size_t)row * Dd);
    float4 v = xr[threadIdx.x];

    float s = blockReduceSum(v.x + v.y + v.z + v.w);
    __shared__ float mean_s, inv_s;
    if (threadIdx.x == 0) mean_s = s * (1.0f / Dd);
    __syncthreads();
    float mean = mean_s;

    float dx = v.x - mean, dy = v.y - mean, dz = v.z - mean, dw = v.w - mean;
    float sq = blockReduceSum(dx * dx + dy * dy + dz * dz + dw * dw);
    if (threadIdx.x == 0) inv_s = 1.0f / (sqrtf(sq * (1.0f / (Dd - 1))) + 1e-6f);
    __syncthreads();
    float inv = inv_s;

    float4 av = ((const float4*)a)[threadIdx.x];
    float4 bv = ((const float4*)bvec)[threadIdx.x];
    uint2 o;
    o.x = packh2(av.x * dx * inv + bv.x, av.y * dy * inv + bv.y);
    o.y = packh2(av.z * dz * inv + bv.z, av.w * dw * inv + bv.w);
    *(uint2*)(h + (size_t)row * Dd + threadIdx.x * 4) = o;
}

// All 4 weights in one launch; blockIdx.y selects the pair.
__global__ __launch_bounds__(256) void whalf4_kernel(
    const float* __restrict__ s0, const float* __restrict__ s1,
    const float* __restrict__ s2, const float* __restrict__ s3,
    __half* __restrict__ d0, __half* __restrict__ d1,
    __half* __restrict__ d2, __half* __restrict__ d3)
{
    int z = blockIdx.y;
    const float* src = (z == 0) ? s0 : (z == 1) ? s1 : (z == 2) ? s2 : s3;
    __half* dst      = (z == 0) ? d0 : (z == 1) ? d1 : (z == 2) ? d2 : d3;
    int i = blockIdx.x * 256 + threadIdx.x;
    float4 v = ((const float4*)src)[i];
    uint2 o;
    o.x = packh2(v.x, v.y);
    o.y = packh2(v.z, v.w);
    *(uint2*)(dst + (size_t)i * 4) = o;
}

// ---------------------------------------------------------------------------
// fp16 GEMM core (ldmatrix fragments), 3-stage cp.async pipeline.
// BM=128, BN=128, BK=64, 8 warps.
// QKV==1: blockIdx.z selects Q/K/V weight + scatter epilogue (Q pre-scaled).
// QKV==0: FC (+bias+residual, fp32 out).
// ---------------------------------------------------------------------------
template<int QKV>
__global__ __launch_bounds__(256, 2) void gemm_h(
    const __half* __restrict__ A,
    const __half* __restrict__ w0, const __half* __restrict__ w1,
    const __half* __restrict__ w2,
    const float* __restrict__ b0, const float* __restrict__ b1,
    const float* __restrict__ b2,
    const float* __restrict__ xres,
    void* __restrict__ c0, void* __restrict__ c1, void* __restrict__ c2)
{
    extern __shared__ __align__(16) __half hsm[];
    const int AST = 9216, BOFF = 27648;    // A stages @0/9216/18432, B @27648+
    uint32_t smem_u = (uint32_t)__cvta_generic_to_shared(hsm);

    int z = QKV ? blockIdx.z : 0;
    const __half* B    = (z == 0) ? w0 : (z == 1) ? w1 : w2;
    const float* bias  = (z == 0) ? b0 : (z == 1) ? b1 : b2;
    float osc = (QKV && z == 0) ? EXP_SC : 1.0f;   // fold exp scale into Q

    const int K = Dd;
    int tid = threadIdx.x;
    int m0 = blockIdx.y * 128, n0 = blockIdx.x * 128;
    int lane = tid & 31, warp = tid >> 5;
    int wm = warp >> 2, wn = warp & 3;
    int g = lane >> 2, tig = lane & 3;
    int mb = wm * 64, nb = wn * 32;

    int aRow = lane & 15;
    int aCol = (lane >> 4) << 3;
    int bRow = ((lane >> 4) << 3) + (lane & 7);
    int bCol = ((lane >> 3) & 1) << 3;

    float acc[4][4][4] = {};

    int r_ld = tid >> 3;
    int c_ld = (tid & 7) * 8;

    auto loadTile = [&](int kt, int s) {
        int kof = kt * 64;
        #pragma unroll
        for (int i = 0; i < 4; i++) {
            int r = r_ld + i * 32;
            CP16(smem_u + (s * AST + r * 72 + c_ld) * 2,
                 A + (size_t)(m0 + r) * K + kof + c_ld);
        }
        #pragma unroll
        for (int i = 0; i < 4; i++) {
            int r = r_ld + i * 32;
            CP16(smem_u + (BOFF + s * AST + r * 72 + c_ld) * 2,
                 B + (size_t)(n0 + r) * K + kof + c_ld);
        }
    };

    loadTile(0, 0);
    CP_COMMIT();
    loadTile(1, 1);
    CP_COMMIT();

    for (int it = 0; it < 16; it++) {
        int s = it % 3;
        if (it < 15) { CP_WAIT(1); } else { CP_WAIT(0); }
        __syncthreads();            // tile it ready; stage (it+2)%3 free

        if (it + 2 < 16) {
            loadTile(it + 2, (it + 2) % 3);
            CP_COMMIT();
        }

        int sa = s * AST, sb = BOFF + s * AST;
        #pragma unroll
        for (int ks = 0; ks < 4; ks++) {
            int kb = ks * 16;
            uint32_t a[4][4], b4[2][4];
            #pragma unroll
            for (int i = 0; i < 4; i++)
                LDSM4(a[i][0], a[i][1], a[i][2], a[i][3],
                      smem_u + (sa + (mb + i * 16 + aRow) * 72 + kb + aCol) * 2);
            #pragma unroll
            for (int jp = 0; jp < 2; jp++)
                LDSM4(b4[jp][0], b4[jp][1], b4[jp][2], b4[jp][3],
                      smem_u + (sb + (nb + jp * 16 + bRow) * 72 + kb + bCol) * 2);
            #pragma unroll
            for (int i = 0; i < 4; i++)
                #pragma unroll
                for (int j = 0; j < 4; j++) {
                    uint32_t bb[2] = { b4[j >> 1][(j & 1) * 2],
                                       b4[j >> 1][(j & 1) * 2 + 1] };
                    MMA_F16(acc[i][j], a[i], bb);
                }
        }
    }

    #pragma unroll
    for (int i = 0; i < 4; i++) {
        int gm = m0 + mb + i * 16 + g;
        #pragma unroll
        for (int j = 0; j < 4; j++) {
            int gn = n0 + nb + j * 8 + tig * 2;
            #pragma unroll
            for (int half_ = 0; half_ < 2; half_++) {
                int m = gm + half_ * 8;
                float v0 = acc[i][j][half_ * 2];
                float v1 = acc[i][j][half_ * 2 + 1];
                if (!QKV) {
                    float* C = (float*)c0;
                    size_t idx = (size_t)m * Dd + gn;
                    float2 xv = *(const float2*)&xres[idx];
                    *(float2*)&C[idx] = make_float2(v0 + b0[gn] + xv.x,
                                                    v1 + b0[gn + 1] + xv.y);
                } else {
                    int bi = m >> 11, s2 = m & (Ss - 1);
                    int hh = gn >> 6, d = gn & 63;
                    if (z < 2) {
                        __half* C = (__half*)((z == 0) ? c0 : c1);
                        uint32_t pv = packh2((v0 + bias[gn]) * osc,
                                             (v1 + bias[gn + 1]) * osc);
                        *(uint32_t*)&C[(((size_t)(bi * Hh + hh) * Ss) + s2) * DK + d] = pv;
                    } else {
                        __half* C = (__half*)c2;
                        size_t base = ((size_t)(bi * Hh + hh) * DK + d) * Ss + s2;
                        C[base]      = __float2half(v0 + bias[gn]);
                        C[base + Ss] = __float2half(v1 + bias[gn + 1]);
                    }
                }
            }
        }
    }
}

// ---------------------------------------------------------------------------
// Fused attention: fp16 mma + ldmatrix, bitmask fast path, no-max softmax,
// f16x2 ex2, unnormalized AV with end-scaling, hoisted pass-B Q fragments.
// ---------------------------------------------------------------------------
__global__ __launch_bounds__(256, 2) void attn_fused(
    const __half* __restrict__ Q, const __half* __restrict__ Kk,
    const __half* __restrict__ Vt, const uint32_t* __restrict__ mbits,
    float* __restrict__ attn, __half* __restrict__ O)
{
    extern __shared__ __align__(16) __half hsm[];
    float* fsm = (float*)hsm;
    const int KA = 9216, KB = 9216, VB = 18432;
    const int WSS = 13824, SMI = 14336;
    uint32_t smem_u = (uint32_t)__cvta_generic_to_shared(hsm);

    int tid = threadIdx.x;
    int bz = blockIdx.y;               // bh
    int m0 = blockIdx.x * 128;
    const __half* Qp = Q  + (size_t)bz * Ss * DK;
    const __half* Kp = Kk + (size_t)bz * Ss * DK;
    const __half* Vp = Vt + (size_t)bz * DK * Ss;
    const uint32_t* mb_ = mbits + (size_t)(bz >> 4) * Ss * (Ss / 32);
    float* arow = attn + (size_t)bz * Ss * Ss;

    int lane = tid & 31, warp = tid >> 5;
    int wm = warp >> 2, wn = warp & 3;
    int g = lane >> 2, tig = lane & 3;
    int mbA = wm * 64;
    int mbB = warp * 16;

    int aRow = lane & 15;
    int aCol = (lane >> 4) << 3;
    int bRow = ((lane >> 4) << 3) + (lane & 7);
    int bCol = ((lane >> 3) & 1) << 3;

    // ---- load Q strip + first K tile ----
    #pragma unroll
    for (int i = 0; i < 4; i++) {
        int idx = tid + i * 256;
        int r = idx >> 3, c = (idx & 7) * 8;
        CP16(smem_u + (r * 72 + c) * 2, Qp + (size_t)(m0 + r) * DK + c);
    }
    #pragma unroll
    for (int i = 0; i < 4; i++) {
        int idx = tid + i * 256;
        int r = idx >> 3, c = (idx & 7) * 8;
        CP16(smem_u + (KA + r * 72 + c) * 2, Kp + (size_t)r * DK + c);
    }
    CP_COMMIT();

    float zs[8];
    #pragma unroll
    for (int s8 = 0; s8 < 8; s8++) zs[s8] = 0.0f;

    // ================= pass A: Z only =================
    for (int kt = 0; kt < 16; kt++) {
        CP_WAIT(0);
        __syncthreads();

        if (kt + 1 < 16) {
            int bo = KA + ((kt + 1) & 1) * 9216;
            #pragma unroll
            for (int i = 0; i < 4; i++) {
                int idx = tid + i * 256;
                int r = idx >> 3, c = (idx & 7) * 8;
                CP16(smem_u + (bo + r * 72 + c) * 2,
                     Kp + (size_t)((kt + 1) * 128 + r) * DK + c);
            }
            CP_COMMIT();
        }

        int ko = KA + (kt & 1) * 9216;
        float acc[4][4][4] = {};
        #pragma unroll
        for (int ks = 0; ks < 4; ks++) {
            int kb = ks * 16;
            uint32_t a[4][4], b4[2][4];
            #pragma unroll
            for (int i = 0; i < 4; i++)
                LDSM4(a[i][0], a[i][1], a[i][2], a[i][3],
                      smem_u + ((mbA + i * 16 + aRow) * 72 + kb + aCol) * 2);
            #pragma unroll
            for (int jp = 0; jp < 2; jp++)
                LDSM4(b4[jp][0], b4[jp][1], b4[jp][2], b4[jp][3],
                      smem_u + (ko + (wn * 32 + jp * 16 + bRow) * 72 + kb + bCol) * 2);
            #pragma unroll
            for (int i = 0; i < 4; i++)
                #pragma unroll
                for (int j = 0; j < 4; j++) {
                    uint32_t bb[2] = { b4[j >> 1][(j & 1) * 2],
                                       b4[j >> 1][(j & 1) * 2 + 1] };
                    MMA_F16(acc[i][j], a[i], bb);
                }
        }

        // epilogue: exp-sum; f16x2 ex2 fast path
        #pragma unroll
        for (int i = 0; i < 4; i++) {
            #pragma unroll
            for (int half_ = 0; half_ < 2; half_++) {
                int s8 = i * 2 + half_;
                int m = m0 + mbA + i * 16 + half_ * 8 + g;
                uint32_t bm = mb_[(size_t)m * 64 + kt * 4 + wn];
                float se = 0.0f;
                if (bm == 0xffffffffu) {
                    #pragma unroll
                    for (int j = 0; j < 4; j++) {
                        float2 pf = h2f2(h2ex2(packh2(acc[i][j][half_ * 2],
                                                      acc[i][j][half_ * 2 + 1])));
                        se += pf.x + pf.y;
                    }
                } else {
                    #pragma unroll
                    for (int j = 0; j < 4; j++) {
                        int bp = j * 8 + tig * 2;
                        if ((bm >> bp) & 1)
                            se += ex2f(acc[i][j][half_ * 2]);
                        if ((bm >> (bp + 1)) & 1)
                            se += ex2f(acc[i][j][half_ * 2 + 1]);
                    }
                }
                zs[s8] += se;
            }
        }
    }

    // quad-reduce, per-warp partials
    #pragma unroll
    for (int s8 = 0; s8 < 8; s8++) {
        zs[s8] += __shfl_xor_sync(0xffffffffu, zs[s8], 1);
        zs[s8] += __shfl_xor_sync(0xffffffffu, zs[s8], 2);
    }
    if (tig == 0) {
        #pragma unroll
        for (int s8 = 0; s8 < 8; s8++) {
            int rloc = mbA + (s8 >> 1) * 16 + (s8 & 1) * 8 + g;
            fsm[WSS + rloc * 4 + wn] = zs[s8];
        }
    }
    __syncthreads();

    // preload pass-B tile 0
    #pragma unroll
    for (int i = 0; i < 2; i++) {
        int idx = tid + i * 256;
        int r = idx >> 3, c = (idx & 7) * 8;
        CP16(smem_u + (KB + r * 72 + c) * 2, Kp + (size_t)r * DK + c);
        CP16(smem_u + (VB + r * 72 + c) * 2, Vp + (size_t)r * Ss + c);
    }
    CP_COMMIT();

    if (tid < 128) {
        float Z = fsm[WSS + tid * 4] + fsm[WSS + tid * 4 + 1] +
                  fsm[WSS + tid * 4 + 2] + fsm[WSS + tid * 4 + 3];
        fsm[SMI + tid] = 1.0f / Z;
    }
    __syncthreads();

    float invlo = fsm[SMI + mbB + g];
    float invhi = fsm[SMI + mbB + g + 8];

    // hoist pass-B Q fragments (invariant across all 32 tiles; Q smem region
    // [0, 9216) is not overwritten by pass-B buffers at 9216+)
    uint32_t qa[4][4];
    #pragma unroll
    for (int ks = 0; ks < 4; ks++)
        LDSM4(qa[ks][0], qa[ks][1], qa[ks][2], qa[ks][3],
              smem_u + ((mbB + aRow) * 72 + ks * 16 + aCol) * 2);

    // ================= pass B =================
    float oacc[8][4] = {};

    for (int tt = 0; tt < 32; tt++) {
        CP_WAIT(0);
        __syncthreads();

        if (tt + 1 < 32) {
            int kbo = KB + ((tt + 1) & 1) * 4608;
            int vbo = VB + ((tt + 1) & 1) * 4608;
            #pragma unroll
            for (int i = 0; i < 2; i++) {
                int idx = tid + i * 256;
                int r = idx >> 3, c = (idx & 7) * 8;
                CP16(smem_u + (kbo + r * 72 + c) * 2,
                     Kp + (size_t)((tt + 1) * 64 + r) * DK + c);
                CP16(smem_u + (vbo + r * 72 + c) * 2,
                     Vp + (size_t)r * Ss + (tt + 1) * 64 + c);
            }
            CP_COMMIT();
        }

        int ko = KB + (tt & 1) * 4608;
        int vo = VB + (tt & 1) * 4608;

        // --- S for all 64 keys, warp-exclusive rows mbB..mbB+15 ---
        float sacc[8][4] = {};
        #pragma unroll
        for (int ks = 0; ks < 4; ks++) {
            int kb = ks * 16;
            uint32_t b4[4][4];
            #pragma unroll
            for (int jp = 0; jp < 4; jp++)
                LDSM4(b4[jp][0], b4[jp][1], b4[jp][2], b4[jp][3],
                      smem_u + (ko + (jp * 16 + bRow) * 72 + kb + bCol) * 2);
            #pragma unroll
            for (int j = 0; j < 8; j++) {
                uint32_t bb[2] = { b4[j >> 1][(j & 1) * 2],
                                   b4[j >> 1][(j & 1) * 2 + 1] };
                MMA_F16(sacc[j], qa[ks], bb);
            }
        }

        // --- epilogue: unnormalized p via f16x2 ex2; store normalized ---
        uint32_t pA[8][2];
        int mlo = m0 + mbB + g, mhi = mlo + 8;
        uint2 bmlo = *(const uint2*)&mb_[(size_t)mlo * 64 + tt * 2];
        uint2 bmhi = *(const uint2*)&mb_[(size_t)mhi * 64 + tt * 2];
        bool allones = (bmlo.x & bmlo.y & bmhi.x & bmhi.y) == 0xffffffffu;
        if (allones) {
            #pragma unroll
            for (int j = 0; j < 8; j++) {
                int gn = tt * 64 + j * 8 + tig * 2;
                size_t i0 = (size_t)mlo * Ss + gn;
                size_t i1 = (size_t)mhi * Ss + gn;
                uint32_t plo = h2ex2(packh2(sacc[j][0], sacc[j][1]));
                uint32_t phi = h2ex2(packh2(sacc[j][2], sacc[j][3]));
                float2 flo = h2f2(plo);
                float2 fhi = h2f2(phi);
                *(float2*)&arow[i0] = make_float2(flo.x * invlo, flo.y * invlo);
                *(float2*)&arow[i1] = make_float2(fhi.x * invhi, fhi.y * invhi);
                pA[j][0] = plo;
                pA[j][1] = phi;
            }
        } else {
            #pragma unroll
            for (int j = 0; j < 8; j++) {
                int gn = tt * 64 + j * 8 + tig * 2;
                size_t i0 = (size_t)mlo * Ss + gn;
                size_t i1 = (size_t)mhi * Ss + gn;
                int sh = (j * 8 + tig * 2) & 31;
                uint32_t wlo = (j < 4) ? bmlo.x : bmlo.y;
                uint32_t whi = (j < 4) ? bmhi.x : bmhi.y;
                float p0 = ((wlo >> sh) & 1)       ? ex2f(sacc[j][0]) : 0.0f;
                float p1 = ((wlo >> (sh + 1)) & 1) ? ex2f(sacc[j][1]) : 0.0f;
                float p2 = ((whi >> sh) & 1)       ? ex2f(sacc[j][2]) : 0.0f;
                float p3 = ((whi >> (sh + 1)) & 1) ? ex2f(sacc[j][3]) : 0.0f;
                *(float2*)&arow[i0] = make_float2(p0 * invlo, p1 * invlo);
                *(float2*)&arow[i1] = make_float2(p2 * invhi, p3 * invhi);
                pA[j][0] = packh2(p0, p1);
                pA[j][1] = packh2(p2, p3);
            }
        }

        // --- AV with unnormalized p (scaled at the end) ---
        #pragma unroll
        for (int q = 0; q < 4; q++) {
            uint32_t a[4];
            a[0] = pA[2 * q][0];
            a[1] = pA[2 * q][1];
            a[2] = pA[2 * q + 1][0];
            a[3] = pA[2 * q + 1][1];

            int kb = q * 16;
            uint32_t b4[4][4];
            #pragma unroll
            for (int jp = 0; jp < 4; jp++)
                LDSM4(b4[jp][0], b4[jp][1], b4[jp][2], b4[jp][3],
                      smem_u + (vo + (jp * 16 + bRow) * 72 + kb + bCol) * 2);
            #pragma unroll
            for (int j2 = 0; j2 < 8; j2++) {
                uint32_t bb[2] = { b4[j2 >> 1][(j2 & 1) * 2],
                                   b4[j2 >> 1][(j2 & 1) * 2 + 1] };
                MMA_F16(oacc[j2], a, bb);
            }
        }
    }

    // ---- O epilogue: scale by invZ here (fp16 O feeds FC) ----
    int bi = bz >> 4, hh = bz & 15;
    int mlo = m0 + mbB + g;
    #pragma unroll
    for (int j2 = 0; j2 < 8; j2++) {
        int d = hh * 64 + j2 * 8 + tig * 2;
        *(uint32_t*)&O[((size_t)bi * Ss + mlo) * Dd + d] =
            packh2(oacc[j2][0] * invlo, oacc[j2][1] * invlo);
        *(uint32_t*)&O[((size_t)bi * Ss + mlo + 8) * Dd + d] =
            packh2(oacc[j2][2] * invhi, oacc[j2][3] * invhi);
    }
}

// ---------------------------------------------------------------------------
extern "C" void kernel_launch(void* const* d_in, const int* in_sizes, int n_in,
                              void* d_out, int out_size)
{
    const float* x    = (const float*)d_in[0];
    const int*   mask = (const int*)d_in[1];
    const float* ln_a = (const float*)d_in[2];
    const float* ln_b = (const float*)d_in[3];
    const float* wq_w = (const float*)d_in[4];
    const float* wq_b = (const float*)d_in[5];
    const float* wk_w = (const float*)d_in[6];
    const float* wk_b = (const float*)d_in[7];
    const float* wv_w = (const float*)d_in[8];
    const float* wv_b = (const float*)d_in[9];
    const float* fc_w = (const float*)d_in[10];
    const float* fc_b = (const float*)d_in[11];
    float* out = (float*)d_out;

    void *ph, *pq, *pk, *pvt, *po, *pwq, *pwk, *pwv, *pwf, *pmb;
    cudaGetSymbolAddress(&ph,  g_h);
    cudaGetSymbolAddress(&pq,  g_q);
    cudaGetSymbolAddress(&pk,  g_k);
    cudaGetSymbolAddress(&pvt, g_vt);
    cudaGetSymbolAddress(&po,  g_o);
    cudaGetSymbolAddress(&pwq, g_wq);
    cudaGetSymbolAddress(&pwk, g_wk);
    cudaGetSymbolAddress(&pwv, g_wv);
    cudaGetSymbolAddress(&pwf, g_wf);
    cudaGetSymbolAddress(&pmb, g_mbits);
    __half* h   = (__half*)ph;
    __half* q   = (__half*)pq;
    __half* k   = (__half*)pk;
    __half* vt  = (__half*)pvt;
    __half* o   = (__half*)po;

    float* attn = out + OUT_ELEMS;

    const int DSM_G = 110592;      // 3-stage pipeline
    const int DSM_A = 57856;
    cudaFuncSetAttribute(gemm_h<1>, cudaFuncAttributeMaxDynamicSharedMemorySize, DSM_G);
    cudaFuncSetAttribute(gemm_h<0>, cudaFuncAttributeMaxDynamicSharedMemorySize, DSM_G);
    cudaFuncSetAttribute(attn_fused, cudaFuncAttributeMaxDynamicSharedMemorySize, DSM_A);

    // 0a. mask -> bitmap
    mask_bits_kernel<<<(Bb * Ss * (Ss / 32)) / 256, 256>>>(mask, (uint32_t*)pmb);

    // 0b. Weights -> fp16 (one launch)
    whalf4_kernel<<<dim3(1024, 4), 256>>>(
        wq_w, wk_w, wv_w, fc_w,
        (__half*)pwq, (__half*)pwk, (__half*)pwv, (__half*)pwf);

    // 1. LayerNorm (fp16 out)
    ln_kernel<<<Bb * Ss, 256>>>(x, ln_a, ln_b, h);

    // 2. QKV projections (single z-indexed launch; Q pre-scaled by EXP_SC)
    gemm_h<1><<<dim3(8, 64, 3), 256, DSM_G>>>(
        h, (__half*)pwq, (__half*)pwk, (__half*)pwv,
        wq_b, wk_b, wv_b, nullptr, q, k, vt);

    // 3+4+5. Fused attention
    attn_fused<<<dim3(16, Bb * Hh), 256, DSM_A>>>(
        q, k, vt, (const uint32_t*)pmb, attn, o);

    // 6. FC + bias + residual
    gemm_h<0><<<dim3(8, 64, 1), 256, DSM_G>>>(
        o, (__half*)pwf, nullptr, nullptr,
        fc_b, nullptr, nullptr, x, out, nullptr, nullptr);
}

// round 17
// speedup vs baseline: 1.0891x; 1.0123x over previous
#include <cuda_runtime.h>
#include <cuda_fp16.h>
#include <math.h>
#include <stdint.h>

#define Bb 4
#define Ss 2048
#define Dd 1024
#define Hh 16
#define DK 64

static const size_t OUT_ELEMS = (size_t)Bb * Ss * Dd;   // 8388608

// Scratch (device globals — allocation-free per harness rules)
__device__ __half g_h[(size_t)Bb * Ss * Dd];
__device__ __half g_q[(size_t)Bb * Hh * Ss * DK];
__device__ __half g_k[(size_t)Bb * Hh * Ss * DK];
__device__ __half g_vt[(size_t)Bb * Hh * DK * Ss];  // V^T: [bh][d][s]
__device__ __half g_o[(size_t)Bb * Ss * Dd];
__device__ __half g_wq[(size_t)Dd * Dd];
__device__ __half g_wk[(size_t)Dd * Dd];
__device__ __half g_wv[(size_t)Dd * Dd];
__device__ __half g_wf[(size_t)Dd * Dd];
__device__ uint32_t g_mbits[(size_t)Bb * Ss * (Ss / 32)];   // 1 bit / key

// ---------------------------------------------------------------------------
#define CP16(dst_u32, src_ptr) \
    asm volatile("cp.async.cg.shared.global [%0], [%1], 16;\n" :: "r"(dst_u32), "l"(src_ptr))
#define CP_COMMIT() asm volatile("cp.async.commit_group;\n" ::)
#define CP_WAIT(N)  asm volatile("cp.async.wait_group %0;\n" :: "n"(N))

#define MMA_F16(acc, a, b) \
    asm volatile( \
        "mma.sync.aligned.m16n8k16.row.col.f32.f16.f16.f32 " \
        "{%0,%1,%2,%3}, {%4,%5,%6,%7}, {%8,%9}, {%0,%1,%2,%3};" \
        : "+f"(acc[0]), "+f"(acc[1]), "+f"(acc[2]), "+f"(acc[3]) \
        : "r"(a[0]), "r"(a[1]), "r"(a[2]), "r"(a[3]), "r"(b[0]), "r"(b[1]))

#define LDSM4(R0, R1, R2, R3, ADDR) \
    asm volatile("ldmatrix.sync.aligned.m8n8.x4.shared.b16 {%0,%1,%2,%3}, [%4];" \
        : "=r"(R0), "=r"(R1), "=r"(R2), "=r"(R3) : "r"(ADDR))

__device__ __forceinline__ uint32_t packh2(float lo, float hi) {
    __half2 h = __floats2half2_rn(lo, hi);
    return *(uint32_t*)&h;
}
// Q is pre-scaled by 0.125*log2(e), so exp(0.125*s_raw) = ex2(s)
#define EXP_SC 0.1803368801111244f
__device__ __forceinline__ float ex2f(float x) {
    float r;
    asm("ex2.approx.f32 %0, %1;" : "=f"(r) : "f"(x));
    return r;
}
__device__ __forceinline__ uint32_t h2ex2(uint32_t x) {
    uint32_t r;
    asm("ex2.approx.f16x2 %0, %1;" : "=r"(r) : "r"(x));
    return r;
}
__device__ __forceinline__ float2 h2f2(uint32_t x) {
    __half2 h = *(__half2*)&x;
    return __half22float2(h);
}

__device__ __forceinline__ float blockReduceSum(float val) {
    __shared__ float sh[32];
    int lane = threadIdx.x & 31, wid = threadIdx.x >> 5;
    #pragma unroll
    for (int o = 16; o; o >>= 1) val += __shfl_down_sync(0xffffffffu, val, o);
    if (lane == 0) sh[wid] = val;
    __syncthreads();
    val = (threadIdx.x < 8) ? sh[lane] : 0.0f;
    if (wid == 0) {
        #pragma unroll
        for (int o = 4; o; o >>= 1) val += __shfl_down_sync(0xffffffffu, val, o);
    }
    __syncthreads();
    return val;
}

// ---------------------------------------------------------------------------
// mask (int32) -> bitmap (1 bit per element), warp-ballot, fully coalesced
// ---------------------------------------------------------------------------
__global__ __launch_bounds__(256) void mask_bits_kernel(
    const int* __restrict__ mask, uint32_t* __restrict__ bits)
{
    int warp = threadIdx.x >> 5, lane = threadIdx.x & 31;
    size_t w0 = (size_t)blockIdx.x * 256 + warp * 32;
    #pragma unroll 4
    for (int i = 0; i < 32; i++) {
        size_t w = w0 + i;
        int v = mask[w * 32 + lane];
        uint32_t bm = __ballot_sync(0xffffffffu, v != 0);
        if (lane == 0) bits[w] = bm;
    }
}

// ---------------------------------------------------------------------------
// LayerNorm — writes fp16 h
// ---------------------------------------------------------------------------
__global__ __launch_bounds__(256) void ln_kernel(
    const float* __restrict__ x, const float* __restrict__ a,
    const float* __restrict__ bvec, __half* __restrict__ h)
{
    int row = blockIdx.x;
    const float4* xr = (const float4*)(x + (size_t)row * Dd);
    float4 v = xr[threadIdx.x];

    float s = blockReduceSum(v.x + v.y + v.z + v.w);
    __shared__ float mean_s, inv_s;
    if (threadIdx.x == 0) mean_s = s * (1.0f / Dd);
    __syncthreads();
    float mean = mean_s;

    float dx = v.x - mean, dy = v.y - mean, dz = v.z - mean, dw = v.w - mean;
    float sq = blockReduceSum(dx * dx + dy * dy + dz * dz + dw * dw);
    if (threadIdx.x == 0) inv_s = 1.0f / (sqrtf(sq * (1.0f / (Dd - 1))) + 1e-6f);
    __syncthreads();
    float inv = inv_s;

    float4 av = ((const float4*)a)[threadIdx.x];
    float4 bv = ((const float4*)bvec)[threadIdx.x];
    uint2 o;
    o.x = packh2(av.x * dx * inv + bv.x, av.y * dy * inv + bv.y);
    o.y = packh2(av.z * dz * inv + bv.z, av.w * dw * inv + bv.w);
    *(uint2*)(h + (size_t)row * Dd + threadIdx.x * 4) = o;
}

// All 4 weights in one launch; blockIdx.y selects the pair.
__global__ __launch_bounds__(256) void whalf4_kernel(
    const float* __restrict__ s0, const float* __restrict__ s1,
    const float* __restrict__ s2, const float* __restrict__ s3,
    __half* __restrict__ d0, __half* __restrict__ d1,
    __half* __restrict__ d2, __half* __restrict__ d3)
{
    int z = blockIdx.y;
    const float* src = (z == 0) ? s0 : (z == 1) ? s1 : (z == 2) ? s2 : s3;
    __half* dst      = (z == 0) ? d0 : (z == 1) ? d1 : (z == 2) ? d2 : d3;
    int i = blockIdx.x * 256 + threadIdx.x;
    float4 v = ((const float4*)src)[i];
    uint2 o;
    o.x = packh2(v.x, v.y);
    o.y = packh2(v.z, v.w);
    *(uint2*)(dst + (size_t)i * 4) = o;
}

// ---------------------------------------------------------------------------
// fp16 GEMM core (ldmatrix fragments), 2-stage cp.async pipeline.
// BM=128, BN=128, BK=64, 8 warps.
// QKV==1: blockIdx.z selects Q/K/V weight + scatter epilogue (Q pre-scaled).
// QKV==0: FC (+bias+residual, fp32 out).
// ---------------------------------------------------------------------------
template<int QKV>
__global__ __launch_bounds__(256, 2) void gemm_h(
    const __half* __restrict__ A,
    const __half* __restrict__ w0, const __half* __restrict__ w1,
    const __half* __restrict__ w2,
    const float* __restrict__ b0, const float* __restrict__ b1,
    const float* __restrict__ b2,
    const float* __restrict__ xres,
    void* __restrict__ c0, void* __restrict__ c1, void* __restrict__ c2)
{
    extern __shared__ __align__(16) __half hsm[];
    const int AST = 9216, BOFF = 18432;    // half units
    uint32_t smem_u = (uint32_t)__cvta_generic_to_shared(hsm);

    int z = QKV ? blockIdx.z : 0;
    const __half* B    = (z == 0) ? w0 : (z == 1) ? w1 : w2;
    const float* bias  = (z == 0) ? b0 : (z == 1) ? b1 : b2;
    float osc = (QKV && z == 0) ? EXP_SC : 1.0f;   // fold exp scale into Q

    const int K = Dd;
    int tid = threadIdx.x;
    int m0 = blockIdx.y * 128, n0 = blockIdx.x * 128;
    int lane = tid & 31, warp = tid >> 5;
    int wm = warp >> 2, wn = warp & 3;
    int g = lane >> 2, tig = lane & 3;
    int mb = wm * 64, nb = wn * 32;

    int aRow = lane & 15;
    int aCol = (lane >> 4) << 3;
    int bRow = ((lane >> 4) << 3) + (lane & 7);
    int bCol = ((lane >> 3) & 1) << 3;

    float acc[4][4][4] = {};

    int r_ld = tid >> 3;
    int c_ld = (tid & 7) * 8;

    auto loadTile = [&](int kt, int s) {
        int kof = kt * 64;
        #pragma unroll
        for (int i = 0; i < 4; i++) {
            int r = r_ld + i * 32;
            CP16(smem_u + (s * AST + r * 72 + c_ld) * 2,
                 A + (size_t)(m0 + r) * K + kof + c_ld);
        }
        #pragma unroll
        for (int i = 0; i < 4; i++) {
            int r = r_ld + i * 32;
            CP16(smem_u + (BOFF + s * AST + r * 72 + c_ld) * 2,
                 B + (size_t)(n0 + r) * K + kof + c_ld);
        }
    };

    loadTile(0, 0);
    CP_COMMIT();

    for (int it = 0; it < 16; it++) {
        int s = it & 1;
        CP_WAIT(0);
        __syncthreads();            // tile it ready; buffer s^1 free

        if (it + 1 < 16) {
            loadTile(it + 1, s ^ 1);
            CP_COMMIT();
        }

        int sa = s * AST, sb = BOFF + s * AST;
        #pragma unroll
        for (int ks = 0; ks < 4; ks++) {
            int kb = ks * 16;
            uint32_t a[4][4], b4[2][4];
            #pragma unroll
            for (int i = 0; i < 4; i++)
                LDSM4(a[i][0], a[i][1], a[i][2], a[i][3],
                      smem_u + (sa + (mb + i * 16 + aRow) * 72 + kb + aCol) * 2);
            #pragma unroll
            for (int jp = 0; jp < 2; jp++)
                LDSM4(b4[jp][0], b4[jp][1], b4[jp][2], b4[jp][3],
                      smem_u + (sb + (nb + jp * 16 + bRow) * 72 + kb + bCol) * 2);
            #pragma unroll
            for (int i = 0; i < 4; i++)
                #pragma unroll
                for (int j = 0; j < 4; j++) {
                    uint32_t bb[2] = { b4[j >> 1][(j & 1) * 2],
                                       b4[j >> 1][(j & 1) * 2 + 1] };
                    MMA_F16(acc[i][j], a[i], bb);
                }
        }
    }

    #pragma unroll
    for (int i = 0; i < 4; i++) {
        int gm = m0 + mb + i * 16 + g;
        #pragma unroll
        for (int j = 0; j < 4; j++) {
            int gn = n0 + nb + j * 8 + tig * 2;
            #pragma unroll
            for (int half_ = 0; half_ < 2; half_++) {
                int m = gm + half_ * 8;
                float v0 = acc[i][j][half_ * 2];
                float v1 = acc[i][j][half_ * 2 + 1];
                if (!QKV) {
                    float* C = (float*)c0;
                    size_t idx = (size_t)m * Dd + gn;
                    float2 xv = *(const float2*)&xres[idx];
                    *(float2*)&C[idx] = make_float2(v0 + b0[gn] + xv.x,
                                                    v1 + b0[gn + 1] + xv.y);
                } else {
                    int bi = m >> 11, s2 = m & (Ss - 1);
                    int hh = gn >> 6, d = gn & 63;
                    if (z < 2) {
                        __half* C = (__half*)((z == 0) ? c0 : c1);
                        uint32_t pv = packh2((v0 + bias[gn]) * osc,
                                             (v1 + bias[gn + 1]) * osc);
                        *(uint32_t*)&C[(((size_t)(bi * Hh + hh) * Ss) + s2) * DK + d] = pv;
                    } else {
                        __half* C = (__half*)c2;
                        size_t base = ((size_t)(bi * Hh + hh) * DK + d) * Ss + s2;
                        C[base]      = __float2half(v0 + bias[gn]);
                        C[base + Ss] = __float2half(v1 + bias[gn + 1]);
                    }
                }
            }
        }
    }
}

// ---------------------------------------------------------------------------
// Fused attention: fp16 mma + ldmatrix, bitmask fast path, no-max softmax,
// f16x2 ex2, unnormalized AV with end-scaling, hoisted pass-B Q fragments.
// ---------------------------------------------------------------------------
__global__ __launch_bounds__(256, 2) void attn_fused(
    const __half* __restrict__ Q, const __half* __restrict__ Kk,
    const __half* __restrict__ Vt, const uint32_t* __restrict__ mbits,
    float* __restrict__ attn, __half* __restrict__ O)
{
    extern __shared__ __align__(16) __half hsm[];
    float* fsm = (float*)hsm;
    const int KA = 9216, KB = 9216, VB = 18432;
    const int WSS = 13824, SMI = 14336;
    uint32_t smem_u = (uint32_t)__cvta_generic_to_shared(hsm);

    int tid = threadIdx.x;
    int bz = blockIdx.y;               // bh
    int m0 = blockIdx.x * 128;
    const __half* Qp = Q  + (size_t)bz * Ss * DK;
    const __half* Kp = Kk + (size_t)bz * Ss * DK;
    const __half* Vp = Vt + (size_t)bz * DK * Ss;
    const uint32_t* mb_ = mbits + (size_t)(bz >> 4) * Ss * (Ss / 32);
    float* arow = attn + (size_t)bz * Ss * Ss;

    int lane = tid & 31, warp = tid >> 5;
    int wm = warp >> 2, wn = warp & 3;
    int g = lane >> 2, tig = lane & 3;
    int mbA = wm * 64;
    int mbB = warp * 16;

    int aRow = lane & 15;
    int aCol = (lane >> 4) << 3;
    int bRow = ((lane >> 4) << 3) + (lane & 7);
    int bCol = ((lane >> 3) & 1) << 3;

    // ---- load Q strip + first K tile ----
    #pragma unroll
    for (int i = 0; i < 4; i++) {
        int idx = tid + i * 256;
        int r = idx >> 3, c = (idx & 7) * 8;
        CP16(smem_u + (r * 72 + c) * 2, Qp + (size_t)(m0 + r) * DK + c);
    }
    #pragma unroll
    for (int i = 0; i < 4; i++) {
        int idx = tid + i * 256;
        int r = idx >> 3, c = (idx & 7) * 8;
        CP16(smem_u + (KA + r * 72 + c) * 2, Kp + (size_t)r * DK + c);
    }
    CP_COMMIT();

    float zs[8];
    #pragma unroll
    for (int s8 = 0; s8 < 8; s8++) zs[s8] = 0.0f;

    // ================= pass A: Z only =================
    for (int kt = 0; kt < 16; kt++) {
        CP_WAIT(0);
        __syncthreads();

        if (kt + 1 < 16) {
            int bo = KA + ((kt + 1) & 1) * 9216;
            #pragma unroll
            for (int i = 0; i < 4; i++) {
                int idx = tid + i * 256;
                int r = idx >> 3, c = (idx & 7) * 8;
                CP16(smem_u + (bo + r * 72 + c) * 2,
                     Kp + (size_t)((kt + 1) * 128 + r) * DK + c);
            }
            CP_COMMIT();
        }

        int ko = KA + (kt & 1) * 9216;
        float acc[4][4][4] = {};
        #pragma unroll
        for (int ks = 0; ks < 4; ks++) {
            int kb = ks * 16;
            uint32_t a[4][4], b4[2][4];
            #pragma unroll
            for (int i = 0; i < 4; i++)
                LDSM4(a[i][0], a[i][1], a[i][2], a[i][3],
                      smem_u + ((mbA + i * 16 + aRow) * 72 + kb + aCol) * 2);
            #pragma unroll
            for (int jp = 0; jp < 2; jp++)
                LDSM4(b4[jp][0], b4[jp][1], b4[jp][2], b4[jp][3],
                      smem_u + (ko + (wn * 32 + jp * 16 + bRow) * 72 + kb + bCol) * 2);
            #pragma unroll
            for (int i = 0; i < 4; i++)
                #pragma unroll
                for (int j = 0; j < 4; j++) {
                    uint32_t bb[2] = { b4[j >> 1][(j & 1) * 2],
                                       b4[j >> 1][(j & 1) * 2 + 1] };
                    MMA_F16(acc[i][j], a[i], bb);
                }
        }

        // epilogue: exp-sum; f16x2 ex2 fast path
        #pragma unroll
        for (int i = 0; i < 4; i++) {
            #pragma unroll
            for (int half_ = 0; half_ < 2; half_++) {
                int s8 = i * 2 + half_;
                int m = m0 + mbA + i * 16 + half_ * 8 + g;
                uint32_t bm = mb_[(size_t)m * 64 + kt * 4 + wn];
                float se = 0.0f;
                if (bm == 0xffffffffu) {
                    #pragma unroll
                    for (int j = 0; j < 4; j++) {
                        float2 pf = h2f2(h2ex2(packh2(acc[i][j][half_ * 2],
                                                      acc[i][j][half_ * 2 + 1])));
                        se += pf.x + pf.y;
                    }
                } else {
                    #pragma unroll
                    for (int j = 0; j < 4; j++) {
                        int bp = j * 8 + tig * 2;
                        if ((bm >> bp) & 1)
                            se += ex2f(acc[i][j][half_ * 2]);
                        if ((bm >> (bp + 1)) & 1)
                            se += ex2f(acc[i][j][half_ * 2 + 1]);
                    }
                }
                zs[s8] += se;
            }
        }
    }

    // quad-reduce, per-warp partials
    #pragma unroll
    for (int s8 = 0; s8 < 8; s8++) {
        zs[s8] += __shfl_xor_sync(0xffffffffu, zs[s8], 1);
        zs[s8] += __shfl_xor_sync(0xffffffffu, zs[s8], 2);
    }
    if (tig == 0) {
        #pragma unroll
        for (int s8 = 0; s8 < 8; s8++) {
            int rloc = mbA + (s8 >> 1) * 16 + (s8 & 1) * 8 + g;
            fsm[WSS + rloc * 4 + wn] = zs[s8];
        }
    }
    __syncthreads();

    // preload pass-B tile 0
    #pragma unroll
    for (int i = 0; i < 2; i++) {
        int idx = tid + i * 256;
        int r = idx >> 3, c = (idx & 7) * 8;
        CP16(smem_u + (KB + r * 72 + c) * 2, Kp + (size_t)r * DK + c);
        CP16(smem_u + (VB + r * 72 + c) * 2, Vp + (size_t)r * Ss + c);
    }
    CP_COMMIT();

    if (tid < 128) {
        float Z = fsm[WSS + tid * 4] + fsm[WSS + tid * 4 + 1] +
                  fsm[WSS + tid * 4 + 2] + fsm[WSS + tid * 4 + 3];
        fsm[SMI + tid] = 1.0f / Z;
    }
    __syncthreads();

    float invlo = fsm[SMI + mbB + g];
    float invhi = fsm[SMI + mbB + g + 8];

    // hoist pass-B Q fragments (invariant across all 32 tiles)
    uint32_t qa[4][4];
    #pragma unroll
    for (int ks = 0; ks < 4; ks++)
        LDSM4(qa[ks][0], qa[ks][1], qa[ks][2], qa[ks][3],
              smem_u + ((mbB + aRow) * 72 + ks * 16 + aCol) * 2);

    // ================= pass B =================
    float oacc[8][4] = {};

    for (int tt = 0; tt < 32; tt++) {
        CP_WAIT(0);
        __syncthreads();

        if (tt + 1 < 32) {
            int kbo = KB + ((tt + 1) & 1) * 4608;
            int vbo = VB + ((tt + 1) & 1) * 4608;
            #pragma unroll
            for (int i = 0; i < 2; i++) {
                int idx = tid + i * 256;
                int r = idx >> 3, c = (idx & 7) * 8;
                CP16(smem_u + (kbo + r * 72 + c) * 2,
                     Kp + (size_t)((tt + 1) * 64 + r) * DK + c);
                CP16(smem_u + (vbo + r * 72 + c) * 2,
                     Vp + (size_t)r * Ss + (tt + 1) * 64 + c);
            }
            CP_COMMIT();
        }

        int ko = KB + (tt & 1) * 4608;
        int vo = VB + (tt & 1) * 4608;

        // --- S for all 64 keys, warp-exclusive rows mbB..mbB+15 ---
        float sacc[8][4] = {};
        #pragma unroll
        for (int ks = 0; ks < 4; ks++) {
            int kb = ks * 16;
            uint32_t b4[4][4];
            #pragma unroll
            for (int jp = 0; jp < 4; jp++)
                LDSM4(b4[jp][0], b4[jp][1], b4[jp][2], b4[jp][3],
                      smem_u + (ko + (jp * 16 + bRow) * 72 + kb + bCol) * 2);
            #pragma unroll
            for (int j = 0; j < 8; j++) {
                uint32_t bb[2] = { b4[j >> 1][(j & 1) * 2],
                                   b4[j >> 1][(j & 1) * 2 + 1] };
                MMA_F16(sacc[j], qa[ks], bb);
            }
        }

        // --- epilogue: unnormalized p via f16x2 ex2; store normalized ---
        uint32_t pA[8][2];
        int mlo = m0 + mbB + g, mhi = mlo + 8;
        uint2 bmlo = *(const uint2*)&mb_[(size_t)mlo * 64 + tt * 2];
        uint2 bmhi = *(const uint2*)&mb_[(size_t)mhi * 64 + tt * 2];
        bool allones = (bmlo.x & bmlo.y & bmhi.x & bmhi.y) == 0xffffffffu;
        if (allones) {
            #pragma unroll
            for (int j = 0; j < 8; j++) {
                int gn = tt * 64 + j * 8 + tig * 2;
                size_t i0 = (size_t)mlo * Ss + gn;
                size_t i1 = (size_t)mhi * Ss + gn;
                uint32_t plo = h2ex2(packh2(sacc[j][0], sacc[j][1]));
                uint32_t phi = h2ex2(packh2(sacc[j][2], sacc[j][3]));
                float2 flo = h2f2(plo);
                float2 fhi = h2f2(phi);
                *(float2*)&arow[i0] = make_float2(flo.x * invlo, flo.y * invlo);
                *(float2*)&arow[i1] = make_float2(fhi.x * invhi, fhi.y * invhi);
                pA[j][0] = plo;
                pA[j][1] = phi;
            }
        } else {
            #pragma unroll
            for (int j = 0; j < 8; j++) {
                int gn = tt * 64 + j * 8 + tig * 2;
                size_t i0 = (size_t)mlo * Ss + gn;
                size_t i1 = (size_t)mhi * Ss + gn;
                int sh = (j * 8 + tig * 2) & 31;
                uint32_t wlo = (j < 4) ? bmlo.x : bmlo.y;
                uint32_t whi = (j < 4) ? bmhi.x : bmhi.y;
                float p0 = ((wlo >> sh) & 1)       ? ex2f(sacc[j][0]) : 0.0f;
                float p1 = ((wlo >> (sh + 1)) & 1) ? ex2f(sacc[j][1]) : 0.0f;
                float p2 = ((whi >> sh) & 1)       ? ex2f(sacc[j][2]) : 0.0f;
                float p3 = ((whi >> (sh + 1)) & 1) ? ex2f(sacc[j][3]) : 0.0f;
                *(float2*)&arow[i0] = make_float2(p0 * invlo, p1 * invlo);
                *(float2*)&arow[i1] = make_float2(p2 * invhi, p3 * invhi);
                pA[j][0] = packh2(p0, p1);
                pA[j][1] = packh2(p2, p3);
            }
        }

        // --- AV with unnormalized p (scaled at the end) ---
        #pragma unroll
        for (int q = 0; q < 4; q++) {
            uint32_t a[4];
            a[0] = pA[2 * q][0];
            a[1] = pA[2 * q][1];
            a[2] = pA[2 * q + 1][0];
            a[3] = pA[2 * q + 1][1];

            int kb = q * 16;
            uint32_t b4[4][4];
            #pragma unroll
            for (int jp = 0; jp < 4; jp++)
                LDSM4(b4[jp][0], b4[jp][1], b4[jp][2], b4[jp][3],
                      smem_u + (vo + (jp * 16 + bRow) * 72 + kb + bCol) * 2);
            #pragma unroll
            for (int j2 = 0; j2 < 8; j2++) {
                uint32_t bb[2] = { b4[j2 >> 1][(j2 & 1) * 2],
                                   b4[j2 >> 1][(j2 & 1) * 2 + 1] };
                MMA_F16(oacc[j2], a, bb);
            }
        }
    }

    // ---- O epilogue: scale by invZ here (fp16 O feeds FC) ----
    int bi = bz >> 4, hh = bz & 15;
    int mlo = m0 + mbB + g;
    #pragma unroll
    for (int j2 = 0; j2 < 8; j2++) {
        int d = hh * 64 + j2 * 8 + tig * 2;
        *(uint32_t*)&O[((size_t)bi * Ss + mlo) * Dd + d] =
            packh2(oacc[j2][0] * invlo, oacc[j2][1] * invlo);
        *(uint32_t*)&O[((size_t)bi * Ss + mlo + 8) * Dd + d] =
            packh2(oacc[j2][2] * invhi, oacc[j2][3] * invhi);
    }
}

// ---------------------------------------------------------------------------
extern "C" void kernel_launch(void* const* d_in, const int* in_sizes, int n_in,
                              void* d_out, int out_size)
{
    const float* x    = (const float*)d_in[0];
    const int*   mask = (const int*)d_in[1];
    const float* ln_a = (const float*)d_in[2];
    const float* ln_b = (const float*)d_in[3];
    const float* wq_w = (const float*)d_in[4];
    const float* wq_b = (const float*)d_in[5];
    const float* wk_w = (const float*)d_in[6];
    const float* wk_b = (const float*)d_in[7];
    const float* wv_w = (const float*)d_in[8];
    const float* wv_b = (const float*)d_in[9];
    const float* fc_w = (const float*)d_in[10];
    const float* fc_b = (const float*)d_in[11];
    float* out = (float*)d_out;

    void *ph, *pq, *pk, *pvt, *po, *pwq, *pwk, *pwv, *pwf, *pmb;
    cudaGetSymbolAddress(&ph,  g_h);
    cudaGetSymbolAddress(&pq,  g_q);
    cudaGetSymbolAddress(&pk,  g_k);
    cudaGetSymbolAddress(&pvt, g_vt);
    cudaGetSymbolAddress(&po,  g_o);
    cudaGetSymbolAddress(&pwq, g_wq);
    cudaGetSymbolAddress(&pwk, g_wk);
    cudaGetSymbolAddress(&pwv, g_wv);
    cudaGetSymbolAddress(&pwf, g_wf);
    cudaGetSymbolAddress(&pmb, g_mbits);
    __half* h   = (__half*)ph;
    __half* q   = (__half*)pq;
    __half* k   = (__half*)pk;
    __half* vt  = (__half*)pvt;
    __half* o   = (__half*)po;

    float* attn = out + OUT_ELEMS;

    const int DSM_G = 73728;       // 2-stage pipeline (measured faster)
    const int DSM_A = 57856;
    cudaFuncSetAttribute(gemm_h<1>, cudaFuncAttributeMaxDynamicSharedMemorySize, DSM_G);
    cudaFuncSetAttribute(gemm_h<0>, cudaFuncAttributeMaxDynamicSharedMemorySize, DSM_G);
    cudaFuncSetAttribute(attn_fused, cudaFuncAttributeMaxDynamicSharedMemorySize, DSM_A);

    // 0a. mask -> bitmap
    mask_bits_kernel<<<(Bb * Ss * (Ss / 32)) / 256, 256>>>(mask, (uint32_t*)pmb);

    // 0b. Weights -> fp16 (one launch)
    whalf4_kernel<<<dim3(1024, 4), 256>>>(
        wq_w, wk_w, wv_w, fc_w,
        (__half*)pwq, (__half*)pwk, (__half*)pwv, (__half*)pwf);

    // 1. LayerNorm (fp16 out)
    ln_kernel<<<Bb * Ss, 256>>>(x, ln_a, ln_b, h);

    // 2. QKV projections (single z-indexed launch; Q pre-scaled by EXP_SC)
    gemm_h<1><<<dim3(8, 64, 3), 256, DSM_G>>>(
        h, (__half*)pwq, (__half*)pwk, (__half*)pwv,
        wq_b, wk_b, wv_b, nullptr, q, k, vt);

    // 3+4+5. Fused attention
    attn_fused<<<dim3(16, Bb * Hh), 256, DSM_A>>>(
        q, k, vt, (const uint32_t*)pmb, attn, o);

    // 6. FC + bias + residual
    gemm_h<0><<<dim3(8, 64, 1), 256, DSM_G>>>(
        o, (__half*)pwf, nullptr, nullptr,
        fc_b, nullptr, nullptr, x, out, nullptr, nullptr);
}